// round 2
// baseline (speedup 1.0000x reference)
#include <cuda_runtime.h>
#include <cstdint>

#define BATCH 128
#define NNODE 64
#define NF    64
#define C1    256   // fe hidden
#define C2    96    // fe out
#define CN1   256   // fn hidden
#define CN2   64    // fn out

// ---------------- scratch (device globals: no allocations allowed) ----------
__device__ float g_P[BATCH * NNODE * C1];   // x_i @ W0[0:64] + b0
__device__ float g_Q[BATCH * NNODE * C1];   // x_j @ W0[64:128]

__device__ __forceinline__ float lrelu(float v) { return v > 0.f ? v : 0.2f * v; }

#define CP_ASYNC16(smaddr, gptr) \
    asm volatile("cp.async.cg.shared.global [%0], [%1], 16;" :: "r"(smaddr), "l"(gptr))
#define CP_COMMIT() asm volatile("cp.async.commit_group;")
#define CP_WAIT1()  asm volatile("cp.async.wait_group 1;" ::: "memory")
#define CP_WAIT0()  asm volatile("cp.async.wait_group 0;" ::: "memory")

#define PACK2(dst, fv) \
    asm("mov.b64 %0, {%1, %1};" : "=l"(dst) : "r"(__float_as_uint(fv)))
#define FMA2(acc, a, b) \
    asm("fma.rn.f32x2 %0, %1, %2, %0;" : "+l"(acc) : "l"(a), "l"(b))

// ---------------- kernel 1: P/Q precompute -----------------------------------
__global__ __launch_bounds__(256) void pq_kernel(
    const float* __restrict__ x, const float* __restrict__ W0,
    const float* __restrict__ b0)
{
    __shared__ float xs[16 * 64];
    const int r0 = blockIdx.x * 16;         // 8192 rows / 16 = 512 blocks
    const int tid = threadIdx.x;

    ((float4*)xs)[tid] = ((const float4*)(x + (size_t)r0 * 64))[tid];
    __syncthreads();

    const int c = tid;
    float accP[16], accQ[16];
#pragma unroll
    for (int r = 0; r < 16; r++) { accP[r] = 0.f; accQ[r] = 0.f; }

#pragma unroll 4
    for (int f = 0; f < 64; f++) {
        float wp = W0[f * C1 + c];
        float wq = W0[(64 + f) * C1 + c];
#pragma unroll
        for (int r = 0; r < 16; r++) {
            float xv = xs[r * 64 + f];
            accP[r] = fmaf(xv, wp, accP[r]);
            accQ[r] = fmaf(xv, wq, accQ[r]);
        }
    }
    float bias = b0[c];
#pragma unroll
    for (int r = 0; r < 16; r++) {
        g_P[(size_t)(r0 + r) * C1 + c] = accP[r] + bias;
        g_Q[(size_t)(r0 + r) * C1 + c] = accQ[r];
    }
}

// ---------------- main fused kernel ------------------------------------------
// smem layout (bytes)
#define SM_H0   0        // 64*256*4 = 65536
#define SM_H1   65536    // 65536
#define SM_WB   131072   // 2 * 16384 weight double buffer
#define SM_XS   163840   // 64*64*4 = 16384
#define SM_PV   180224   // 1024
#define SM_W0D  181248   // 1024
#define SM_DIST 182272   // 256
#define SM_RED  182528   // 6144
#define SM_AGG  188672   // 384
#define SM_Z    189056   // 1024
#define SMEM_BYTES 190080

__global__ void __launch_bounds__(256, 1) mp_main(
    const float* __restrict__ x,
    const float* __restrict__ W0,
    const float* __restrict__ W1, const float* __restrict__ b1,
    const float* __restrict__ W2, const float* __restrict__ b2,
    const float* __restrict__ Wn0, const float* __restrict__ bn0,
    const float* __restrict__ Wn1, const float* __restrict__ bn1,
    float* __restrict__ out)
{
    extern __shared__ char sm[];
    float* h0s  = (float*)(sm + SM_H0);
    float* h1s  = (float*)(sm + SM_H1);
    float* wb   = (float*)(sm + SM_WB);
    float* xs   = (float*)(sm + SM_XS);
    float* pv   = (float*)(sm + SM_PV);
    float* w0d  = (float*)(sm + SM_W0D);
    float* dist = (float*)(sm + SM_DIST);
    float* red  = (float*)(sm + SM_RED);
    float* agg  = (float*)(sm + SM_AGG);
    float* z    = (float*)(sm + SM_Z);

    const int tid = threadIdx.x;
    const int b = blockIdx.x >> 6;
    const int i = blockIdx.x & 63;

    // -- stage inputs -------------------------------------------------------
    {
        const float4* xin = (const float4*)(x + (size_t)b * NNODE * NF);
        float4* xd = (float4*)xs;
#pragma unroll
        for (int t = 0; t < 4; t++) xd[tid + t * 256] = xin[tid + t * 256];
        pv[tid]  = g_P[(size_t)(b * 64 + i) * C1 + tid];
        w0d[tid] = W0[128 * C1 + tid];
    }
    __syncthreads();

    // -- distances ----------------------------------------------------------
    if (tid < 64) {
        const float* xi = xs + i * 64;
        const float* xj = xs + tid * 64;
        float s = 0.f;
#pragma unroll
        for (int f = 0; f < 64; f++) {
            float d = xj[f] - xi[f] + 1e-12f;
            s = fmaf(d, d, s);
        }
        dist[tid] = sqrtf(s);
    }
    __syncthreads();

    // -- h0 = lrelu(P_i + Q_j + dist*w0d) -----------------------------------
    {
        const float* Qb = g_Q + (size_t)(b * 64) * C1;
        float pc = pv[tid], wc = w0d[tid];
#pragma unroll 8
        for (int j = 0; j < 64; j++) {
            float v = pc + Qb[(size_t)j * C1 + tid] + dist[j] * wc;
            h0s[j * C1 + tid] = lrelu(v);
        }
    }
    __syncthreads();

    // -- GEMM1: h1 = lrelu(h0[64x256] @ W1[256x256] + b1) -------------------
    const int ct = tid & 31;   // c block: ct*8
    const int jt = tid >> 5;   // j block: jt*8
    {
        auto loadW1 = [&](int buf, int k0) {
            unsigned sb = (unsigned)__cvta_generic_to_shared(wb + buf * 4096);
            const float4* g = (const float4*)(W1 + (size_t)k0 * C1);
#pragma unroll
            for (int t = 0; t < 4; t++)
                CP_ASYNC16(sb + (tid + t * 256) * 16, (const void*)(g + tid + t * 256));
            CP_COMMIT();
        };

        unsigned long long acc[32];
#pragma unroll
        for (int r = 0; r < 32; r++) acc[r] = 0ull;

        loadW1(0, 0);
        for (int t = 0; t < 16; t++) {
            if (t < 15) { loadW1((t + 1) & 1, (t + 1) * 16); CP_WAIT1(); }
            else        { CP_WAIT0(); }
            __syncthreads();
            const float* A  = h0s + (jt * 8) * C1 + t * 16;
            const float* Bt = wb + (t & 1) * 4096;       // [16][256]
#pragma unroll
            for (int kk = 0; kk < 16; kk++) {
                unsigned long long ap[8];
#pragma unroll
                for (int r = 0; r < 8; r++) PACK2(ap[r], A[r * C1 + kk]);
                const unsigned long long* Bq =
                    (const unsigned long long*)(Bt + kk * C1 + ct * 8);
                unsigned long long bp[4];
#pragma unroll
                for (int e = 0; e < 4; e++) bp[e] = Bq[e];
#pragma unroll
                for (int r = 0; r < 8; r++)
#pragma unroll
                    for (int e = 0; e < 4; e++) FMA2(acc[r * 4 + e], ap[r], bp[e]);
            }
            __syncthreads();
        }
        // epilogue: bias + lrelu -> h1 smem
#pragma unroll
        for (int e = 0; e < 4; e++) {
            int c0 = ct * 8 + 2 * e;
            float bb0 = b1[c0], bb1 = b1[c0 + 1];
#pragma unroll
            for (int r = 0; r < 8; r++) {
                unsigned long long v = acc[r * 4 + e];
                float lo = lrelu(__uint_as_float((unsigned)v) + bb0);
                float hi = lrelu(__uint_as_float((unsigned)(v >> 32)) + bb1);
                int row = jt * 8 + r;
                h1s[row * C1 + c0]     = lo;
                h1s[row * C1 + c0 + 1] = hi;
            }
        }
    }
    __syncthreads();

    // -- GEMM2: h2 = lrelu(h1[64x256] @ W2[256x96] + b2), then sum over j ---
    const int ct2 = tid & 15;  // c block: ct2*6
    const int jt2 = tid >> 4;  // j block: jt2*4
    {
        auto loadW2 = [&](int buf, int k0) {  // 32x96 floats = 768 float4
            unsigned sb = (unsigned)__cvta_generic_to_shared(wb + buf * 4096);
            const float4* g = (const float4*)(W2 + (size_t)k0 * C2);
#pragma unroll
            for (int t = 0; t < 3; t++)
                CP_ASYNC16(sb + (tid + t * 256) * 16, (const void*)(g + tid + t * 256));
            CP_COMMIT();
        };

        unsigned long long acc2[12];
#pragma unroll
        for (int r = 0; r < 12; r++) acc2[r] = 0ull;

        loadW2(0, 0);
        for (int t = 0; t < 8; t++) {
            if (t < 7) { loadW2((t + 1) & 1, (t + 1) * 32); CP_WAIT1(); }
            else       { CP_WAIT0(); }
            __syncthreads();
            const float* A  = h1s + (jt2 * 4) * C1 + t * 32;
            const float* Bt = wb + (t & 1) * 4096;      // [32][96]
#pragma unroll
            for (int kk = 0; kk < 32; kk++) {
                unsigned long long ap[4];
#pragma unroll
                for (int r = 0; r < 4; r++) PACK2(ap[r], A[r * C1 + kk]);
                const unsigned long long* Bq =
                    (const unsigned long long*)(Bt + kk * C2 + ct2 * 6);
                unsigned long long bp[3];
#pragma unroll
                for (int e = 0; e < 3; e++) bp[e] = Bq[e];
#pragma unroll
                for (int r = 0; r < 4; r++)
#pragma unroll
                    for (int e = 0; e < 3; e++) FMA2(acc2[r * 3 + e], ap[r], bp[e]);
            }
            __syncthreads();
        }
        // epilogue: bias + lrelu, partial row-sum over this thread's 4 rows
        float ps[6];
#pragma unroll
        for (int cc = 0; cc < 6; cc++) ps[cc] = 0.f;
#pragma unroll
        for (int e = 0; e < 3; e++) {
            int c0 = ct2 * 6 + 2 * e;
            float bb0 = b2[c0], bb1 = b2[c0 + 1];
#pragma unroll
            for (int r = 0; r < 4; r++) {
                unsigned long long v = acc2[r * 3 + e];
                ps[2 * e]     += lrelu(__uint_as_float((unsigned)v) + bb0);
                ps[2 * e + 1] += lrelu(__uint_as_float((unsigned)(v >> 32)) + bb1);
            }
        }
#pragma unroll
        for (int cc = 0; cc < 6; cc++) red[jt2 * 96 + ct2 * 6 + cc] = ps[cc];
    }
    __syncthreads();

    if (tid < 96) {
        float s = 0.f;
#pragma unroll
        for (int w = 0; w < 16; w++) s += red[w * 96 + tid];
        agg[tid] = s;
    }
    __syncthreads();

    // -- node MLP -----------------------------------------------------------
    float* t160 = red;                 // reuse (first 160 floats)
    if (tid < 160) t160[tid] = (tid < 96) ? agg[tid] : xs[i * 64 + (tid - 96)];
    __syncthreads();
    {
        float a = bn0[tid];
#pragma unroll 8
        for (int k = 0; k < 160; k++)
            a = fmaf(t160[k], Wn0[(size_t)k * CN1 + tid], a);
        z[tid] = lrelu(a);
    }
    __syncthreads();
    float* part = red + 256;           // 256 floats of partials
    {
        int q = tid >> 6, c = tid & 63;
        float a = 0.f;
#pragma unroll 8
        for (int k = 0; k < 64; k++)
            a = fmaf(z[q * 64 + k], Wn1[(size_t)(q * 64 + k) * CN2 + c], a);
        part[q * 64 + c] = a;
    }
    __syncthreads();
    if (tid < 64) {
        float a = bn1[tid] + part[tid] + part[64 + tid] + part[128 + tid] + part[192 + tid];
        out[(size_t)blockIdx.x * CN2 + tid] = a;
    }
}

// ---------------- launch -----------------------------------------------------
extern "C" void kernel_launch(void* const* d_in, const int* in_sizes, int n_in,
                              void* d_out, int out_size)
{
    const float* x    = (const float*)d_in[0];
    const float* feW0 = (const float*)d_in[1];
    const float* feb0 = (const float*)d_in[2];
    const float* feW1 = (const float*)d_in[3];
    const float* feb1 = (const float*)d_in[4];
    const float* feW2 = (const float*)d_in[5];
    const float* feb2 = (const float*)d_in[6];
    const float* fnW0 = (const float*)d_in[7];
    const float* fnb0 = (const float*)d_in[8];
    const float* fnW1 = (const float*)d_in[9];
    const float* fnb1 = (const float*)d_in[10];
    float* out = (float*)d_out;

    cudaFuncSetAttribute(mp_main, cudaFuncAttributeMaxDynamicSharedMemorySize,
                         SMEM_BYTES);

    pq_kernel<<<512, 256>>>(x, feW0, feb0);
    mp_main<<<BATCH * NNODE, 256, SMEM_BYTES>>>(
        x, feW0, feW1, feb1, feW2, feb2, fnW0, fnb0, fnW1, fnb1, out);
}

// round 4
// speedup vs baseline: 1.9422x; 1.9422x over previous
#include <cuda_runtime.h>
#include <cuda_fp16.h>
#include <cstdint>

#define BATCH 128
#define NN    64
#define C1    256
#define C2    96
#define PA    264          // A smem pitch in halves (528B -> conflict-free)
#define PB    40           // B smem pitch in halves (80B -> conflict-free)
#define THREADS 512

// ---------------- global scratch (zero-initialized device globals) -----------
__device__ float  g_P[BATCH * NN * C1];
__device__ float  g_Q[BATCH * NN * C1];
__device__ __half g_B1[8 * 2 * 256 * PB];   // [kchunk][hi|lo][n=256][k=40pad]
__device__ __half g_B2[8 * 2 * 96 * PB];    // [kchunk][hi|lo][n=96][k=40pad]
__device__ float  g_AGG[BATCH * NN * C2];
__device__ float  g_vec[C1 + C1 + 128];     // w0d | b1 | b2

__device__ __forceinline__ float lrelu(float v) { return v > 0.f ? v : 0.2f * v; }

#define CP_ASYNC16(smaddr, gptr) \
    asm volatile("cp.async.cg.shared.global [%0], [%1], 16;" :: "r"(smaddr), "l"(gptr))
#define CP_COMMIT() asm volatile("cp.async.commit_group;")
#define CP_WAIT0()  asm volatile("cp.async.wait_group 0;" ::: "memory")

__device__ __forceinline__ void hmma(float* c, const uint32_t* a, const uint32_t* b) {
    asm volatile(
        "mma.sync.aligned.m16n8k16.row.col.f32.f16.f16.f32 "
        "{%0,%1,%2,%3}, {%4,%5,%6,%7}, {%8,%9}, {%0,%1,%2,%3};"
        : "+f"(c[0]), "+f"(c[1]), "+f"(c[2]), "+f"(c[3])
        : "r"(a[0]), "r"(a[1]), "r"(a[2]), "r"(a[3]), "r"(b[0]), "r"(b[1]));
}

// ---------------- kernel: P/Q precompute (fp32) ------------------------------
__global__ __launch_bounds__(256) void pq_kernel(
    const float* __restrict__ x, const float* __restrict__ W0,
    const float* __restrict__ b0)
{
    __shared__ float xs[16 * 64];
    const int r0 = blockIdx.x * 16;
    const int tid = threadIdx.x;
    ((float4*)xs)[tid] = ((const float4*)(x + (size_t)r0 * 64))[tid];
    __syncthreads();
    const int c = tid;
    float accP[16], accQ[16];
#pragma unroll
    for (int r = 0; r < 16; r++) { accP[r] = 0.f; accQ[r] = 0.f; }
#pragma unroll 4
    for (int f = 0; f < 64; f++) {
        float wp = W0[f * C1 + c];
        float wq = W0[(64 + f) * C1 + c];
#pragma unroll
        for (int r = 0; r < 16; r++) {
            float xv = xs[r * 64 + f];
            accP[r] = fmaf(xv, wp, accP[r]);
            accQ[r] = fmaf(xv, wq, accQ[r]);
        }
    }
    float bias = b0[c];
#pragma unroll
    for (int r = 0; r < 16; r++) {
        g_P[(size_t)(r0 + r) * C1 + c] = accP[r] + bias;
        g_Q[(size_t)(r0 + r) * C1 + c] = accQ[r];
    }
}

// ---------------- kernel: weight fp16 hi/lo split ----------------------------
__global__ __launch_bounds__(256) void prep_w(
    const float* __restrict__ W1, const float* __restrict__ W2)
{
    int idx = blockIdx.x * 256 + threadIdx.x;
    if (idx < 65536) {                              // B1: 8 x 256 x 32
        int t = idx >> 13, rem = idx & 8191;
        int n = rem >> 5, k = rem & 31;
        float v = W1[(size_t)(t * 32 + k) * C1 + n];
        __half hi = __float2half_rn(v);
        __half lo = __float2half_rn(v - __half2float(hi));
        size_t base = (size_t)t * 2 * 256 * PB;
        g_B1[base + (size_t)n * PB + k] = hi;
        g_B1[base + 256 * PB + (size_t)n * PB + k] = lo;
    } else if (idx - 65536 < 24576) {               // B2: 8 x 96 x 32
        int p = idx - 65536;
        int t = p / 3072, rem = p % 3072;
        int n = rem >> 5, k = rem & 31;
        float v = W2[(size_t)(t * 32 + k) * C2 + n];
        __half hi = __float2half_rn(v);
        __half lo = __float2half_rn(v - __half2float(hi));
        size_t base = (size_t)t * 2 * 96 * PB;
        g_B2[base + (size_t)n * PB + k] = hi;
        g_B2[base + 96 * PB + (size_t)n * PB + k] = lo;
    }
}

__global__ void prep_vec(const float* __restrict__ W0,
                         const float* __restrict__ b1,
                         const float* __restrict__ b2) {
    int t = threadIdx.x;
    g_vec[t] = W0[128 * C1 + t];
    g_vec[C1 + t] = b1[t];
    if (t < C2) g_vec[2 * C1 + t] = b2[t];
}

// ---------------- main mma.sync kernel ---------------------------------------
// smem layout (bytes)
#define OFF_AH   0                         // 128 x 264 halves = 67584
#define OFF_AL   67584                     // 67584
#define OFF_B    135168                    // 2 x 40960 = 81920
#define OFF_PV   217088                    // 2048
#define OFF_W0   219136                    // 1024
#define OFF_B1S  220160                    // 1024
#define OFF_B2S  221184                    // 512
#define OFF_DIST 221696                    // 512
#define SMEM_SZ  222208

__global__ void __launch_bounds__(THREADS, 1) mp_main(const float* __restrict__ x)
{
    extern __shared__ __align__(16) unsigned char sm[];
    const unsigned smb = (unsigned)__cvta_generic_to_shared(sm);
    const int tid = threadIdx.x;
    const int w = tid >> 5, lane = tid & 31;
    const int g = lane >> 2, tig = lane & 3;
    const int wm = w & 3, wn = w >> 2;
    const int b = blockIdx.x >> 5;
    const int i0 = (blockIdx.x & 31) * 2;

    __half* Ah  = (__half*)(sm + OFF_AH);
    __half* Al  = (__half*)(sm + OFF_AL);
    __half* Bsm = (__half*)(sm + OFF_B);
    float* pv   = (float*)(sm + OFF_PV);
    float* w0s  = (float*)(sm + OFF_W0);
    float* b1s  = (float*)(sm + OFF_B1S);
    float* b2s  = (float*)(sm + OFF_B2S);
    float* dst_ = (float*)(sm + OFF_DIST);

    // ---- stage small vectors ----
    if (tid < 256) {
        pv[tid]       = g_P[(size_t)(b * 64 + i0) * C1 + tid];
        pv[256 + tid] = g_P[(size_t)(b * 64 + i0 + 1) * C1 + tid];
        w0s[tid] = g_vec[tid];
        b1s[tid] = g_vec[C1 + tid];
        if (tid < C2) b2s[tid] = g_vec[2 * C1 + tid];
    }
    // ---- distances (128 rows = 2 i's x 64 j) ----
    if (tid < 128) {
        int isel = tid >> 6, j = tid & 63;
        const float* xi = x + ((size_t)b * 64 + i0 + isel) * 64;
        const float* xj = x + ((size_t)b * 64 + j) * 64;
        float s = 0.f;
#pragma unroll
        for (int f = 0; f < 64; f++) {
            float d = xj[f] - xi[f] + 1e-12f;
            s = fmaf(d, d, s);
        }
        dst_[tid] = sqrtf(s);
    }
    __syncthreads();

    // ---- build h0 fp16 hi/lo: 128 x 256 ----
    {
        int r = tid >> 2, kq = (tid & 3) * 64;
        int isel = r >> 6, j = r & 63;
        float dj = dst_[r];
        const float* pvr = pv + isel * 256;
        const float4* q4 = (const float4*)(g_Q + ((size_t)(b * 64 + j)) * 256);
        __half2* ahp = (__half2*)(Ah + r * PA);
        __half2* alp = (__half2*)(Al + r * PA);
#pragma unroll
        for (int g4 = 0; g4 < 16; g4++) {
            int k = kq + g4 * 4;
            float4 q = q4[k >> 2];
            float v0 = lrelu(pvr[k + 0] + q.x + dj * w0s[k + 0]);
            float v1 = lrelu(pvr[k + 1] + q.y + dj * w0s[k + 1]);
            float v2 = lrelu(pvr[k + 2] + q.z + dj * w0s[k + 2]);
            float v3 = lrelu(pvr[k + 3] + q.w + dj * w0s[k + 3]);
            __half h0 = __float2half_rn(v0), h1 = __float2half_rn(v1);
            __half h2 = __float2half_rn(v2), h3 = __float2half_rn(v3);
            ahp[(k >> 1) + 0] = __halves2half2(h0, h1);
            ahp[(k >> 1) + 1] = __halves2half2(h2, h3);
            alp[(k >> 1) + 0] = __halves2half2(
                __float2half_rn(v0 - __half2float(h0)),
                __float2half_rn(v1 - __half2float(h1)));
            alp[(k >> 1) + 1] = __halves2half2(
                __float2half_rn(v2 - __half2float(h2)),
                __float2half_rn(v3 - __half2float(h3)));
        }
    }

    auto loadB = [&](const __half* gsrc, int dstbuf, int bytes) {
        unsigned sb = smb + OFF_B + dstbuf * 40960;
        const char* gp = (const char*)gsrc;
        for (int q = tid * 16; q < bytes; q += THREADS * 16)
            CP_ASYNC16(sb + q, gp + q);
        CP_COMMIT();
    };

    const int m0 = wm * 32;

    // =================== GEMM1: h1 = lrelu(h0 @ W1 + b1) ====================
    float acc[2][8][4];
#pragma unroll
    for (int mf = 0; mf < 2; mf++)
#pragma unroll
        for (int nf = 0; nf < 8; nf++)
#pragma unroll
            for (int e = 0; e < 4; e++) acc[mf][nf][e] = 0.f;

    loadB(g_B1, 0, 40960);
    for (int tc = 0; tc < 8; tc++) {
        int buf = tc & 1;
        CP_WAIT0();
        __syncthreads();
        if (tc < 7) loadB(g_B1 + (size_t)(tc + 1) * 2 * 256 * PB, buf ^ 1, 40960);
        const __half* Bh = Bsm + buf * 20480;
        const __half* Bl = Bh + 256 * PB;
#pragma unroll
        for (int ks = 0; ks < 2; ks++) {
            int kg = tc * 32 + ks * 16;
            uint32_t ah[2][4], al[2][4];
#pragma unroll
            for (int mf = 0; mf < 2; mf++) {
                const __half* base = Ah + (m0 + mf * 16 + g) * PA + kg + 2 * tig;
                ah[mf][0] = *(const uint32_t*)(base);
                ah[mf][1] = *(const uint32_t*)(base + 8 * PA);
                ah[mf][2] = *(const uint32_t*)(base + 8);
                ah[mf][3] = *(const uint32_t*)(base + 8 * PA + 8);
                const __half* basel = Al + (m0 + mf * 16 + g) * PA + kg + 2 * tig;
                al[mf][0] = *(const uint32_t*)(basel);
                al[mf][1] = *(const uint32_t*)(basel + 8 * PA);
                al[mf][2] = *(const uint32_t*)(basel + 8);
                al[mf][3] = *(const uint32_t*)(basel + 8 * PA + 8);
            }
#pragma unroll
            for (int nf = 0; nf < 8; nf++) {
                int n = wn * 64 + nf * 8 + g;
                int kk = ks * 16 + 2 * tig;
                const __half* bb = Bh + n * PB + kk;
                uint32_t bh[2] = { *(const uint32_t*)bb, *(const uint32_t*)(bb + 8) };
                const __half* bbl = Bl + n * PB + kk;
                uint32_t bl2[2] = { *(const uint32_t*)bbl, *(const uint32_t*)(bbl + 8) };
#pragma unroll
                for (int mf = 0; mf < 2; mf++) {
                    hmma(acc[mf][nf], ah[mf], bh);
                    hmma(acc[mf][nf], al[mf], bh);
                    hmma(acc[mf][nf], ah[mf], bl2);
                }
            }
        }
    }
    __syncthreads();
    loadB(g_B2, 0, 15360);   // prefetch GEMM2 chunk 0 while h1 is written

    // ---- h1 epilogue: bias + lrelu, split fp16 hi/lo, overwrite A ----
#pragma unroll
    for (int mf = 0; mf < 2; mf++) {
        int row0 = m0 + mf * 16 + g, row1 = row0 + 8;
#pragma unroll
        for (int nf = 0; nf < 8; nf++) {
            int col = wn * 64 + nf * 8 + 2 * tig;
            float ba = b1s[col], bb = b1s[col + 1];
            float v00 = lrelu(acc[mf][nf][0] + ba), v01 = lrelu(acc[mf][nf][1] + bb);
            float v10 = lrelu(acc[mf][nf][2] + ba), v11 = lrelu(acc[mf][nf][3] + bb);
            __half h00 = __float2half_rn(v00), h01 = __float2half_rn(v01);
            __half h10 = __float2half_rn(v10), h11 = __float2half_rn(v11);
            *(__half2*)(Ah + row0 * PA + col) = __halves2half2(h00, h01);
            *(__half2*)(Ah + row1 * PA + col) = __halves2half2(h10, h11);
            *(__half2*)(Al + row0 * PA + col) = __halves2half2(
                __float2half_rn(v00 - __half2float(h00)),
                __float2half_rn(v01 - __half2float(h01)));
            *(__half2*)(Al + row1 * PA + col) = __halves2half2(
                __float2half_rn(v10 - __half2float(h10)),
                __float2half_rn(v11 - __half2float(h11)));
        }
    }
    __syncthreads();

    // =================== GEMM2: h2 = lrelu(h1 @ W2 + b2) ====================
    float ac2[2][3][4];
#pragma unroll
    for (int mf = 0; mf < 2; mf++)
#pragma unroll
        for (int nf = 0; nf < 3; nf++)
#pragma unroll
            for (int e = 0; e < 4; e++) ac2[mf][nf][e] = 0.f;

    for (int tc = 0; tc < 8; tc++) {
        int buf = tc & 1;
        CP_WAIT0();
        __syncthreads();
        if (tc < 7) loadB(g_B2 + (size_t)(tc + 1) * 2 * 96 * PB, buf ^ 1, 15360);
        const __half* Bh = Bsm + buf * 20480;
        const __half* Bl = Bh + 96 * PB;
#pragma unroll
        for (int ks = 0; ks < 2; ks++) {
            int kg = tc * 32 + ks * 16;
            uint32_t ah[2][4], al[2][4];
#pragma unroll
            for (int mf = 0; mf < 2; mf++) {
                const __half* base = Ah + (m0 + mf * 16 + g) * PA + kg + 2 * tig;
                ah[mf][0] = *(const uint32_t*)(base);
                ah[mf][1] = *(const uint32_t*)(base + 8 * PA);
                ah[mf][2] = *(const uint32_t*)(base + 8);
                ah[mf][3] = *(const uint32_t*)(base + 8 * PA + 8);
                const __half* basel = Al + (m0 + mf * 16 + g) * PA + kg + 2 * tig;
                al[mf][0] = *(const uint32_t*)(basel);
                al[mf][1] = *(const uint32_t*)(basel + 8 * PA);
                al[mf][2] = *(const uint32_t*)(basel + 8);
                al[mf][3] = *(const uint32_t*)(basel + 8 * PA + 8);
            }
#pragma unroll
            for (int nf = 0; nf < 3; nf++) {
                int n = wn * 24 + nf * 8 + g;
                int kk = ks * 16 + 2 * tig;
                const __half* bb = Bh + n * PB + kk;
                uint32_t bh[2] = { *(const uint32_t*)bb, *(const uint32_t*)(bb + 8) };
                const __half* bbl = Bl + n * PB + kk;
                uint32_t bl2[2] = { *(const uint32_t*)bbl, *(const uint32_t*)(bbl + 8) };
#pragma unroll
                for (int mf = 0; mf < 2; mf++) {
                    hmma(ac2[mf][nf], ah[mf], bh);
                    hmma(ac2[mf][nf], al[mf], bh);
                    hmma(ac2[mf][nf], ah[mf], bl2);
                }
            }
        }
    }
    __syncthreads();

    // ---- h2 epilogue: bias + lrelu, stage fp32, then column-sum over j ----
    float* stage = (float*)(sm + OFF_B);   // [128][100]
#pragma unroll
    for (int mf = 0; mf < 2; mf++) {
        int row0 = m0 + mf * 16 + g, row1 = row0 + 8;
#pragma unroll
        for (int nf = 0; nf < 3; nf++) {
            int col = wn * 24 + nf * 8 + 2 * tig;
            float ba = b2s[col], bb = b2s[col + 1];
            stage[row0 * 100 + col]     = lrelu(ac2[mf][nf][0] + ba);
            stage[row0 * 100 + col + 1] = lrelu(ac2[mf][nf][1] + bb);
            stage[row1 * 100 + col]     = lrelu(ac2[mf][nf][2] + ba);
            stage[row1 * 100 + col + 1] = lrelu(ac2[mf][nf][3] + bb);
        }
    }
    __syncthreads();
    if (tid < 192) {
        int isel = tid / 96, c = tid - isel * 96;
        float s = 0.f;
#pragma unroll 8
        for (int r = 0; r < 64; r++) s += stage[(isel * 64 + r) * 100 + c];
        g_AGG[(size_t)(b * 64 + i0 + isel) * C2 + c] = s;
    }
}

// ---------------- node MLP (fp32) --------------------------------------------
__global__ __launch_bounds__(256) void node_kernel(
    const float* __restrict__ x,
    const float* __restrict__ Wn0, const float* __restrict__ bn0,
    const float* __restrict__ Wn1, const float* __restrict__ bn1,
    float* __restrict__ out)
{
    __shared__ float t160[16 * 160];
    __shared__ float zs[16 * 256];
    const int r0 = blockIdx.x * 16;
    const int tid = threadIdx.x;

    for (int idx = tid; idx < 16 * 160; idx += 256) {
        int rr = idx / 160, k = idx - rr * 160;
        t160[idx] = (k < 96) ? g_AGG[(size_t)(r0 + rr) * 96 + k]
                             : x[(size_t)(r0 + rr) * 64 + (k - 96)];
    }
    __syncthreads();
    {
        const int c = tid;
        float acc[16];
        float bb = bn0[c];
#pragma unroll
        for (int r = 0; r < 16; r++) acc[r] = bb;
#pragma unroll 4
        for (int k = 0; k < 160; k++) {
            float wv = Wn0[(size_t)k * 256 + c];
#pragma unroll
            for (int r = 0; r < 16; r++) acc[r] = fmaf(t160[r * 160 + k], wv, acc[r]);
        }
#pragma unroll
        for (int r = 0; r < 16; r++) zs[r * 256 + c] = lrelu(acc[r]);
    }
    __syncthreads();
    for (int pass = 0; pass < 4; pass++) {
        int r = pass * 4 + (tid >> 6), c = tid & 63;
        float a = bn1[c];
#pragma unroll 8
        for (int k = 0; k < 256; k++)
            a = fmaf(zs[r * 256 + k], Wn1[(size_t)k * 64 + c], a);
        out[(size_t)(r0 + r) * 64 + c] = a;
    }
}

// ---------------- launch -----------------------------------------------------
extern "C" void kernel_launch(void* const* d_in, const int* in_sizes, int n_in,
                              void* d_out, int out_size)
{
    const float* x    = (const float*)d_in[0];
    const float* feW0 = (const float*)d_in[1];
    const float* feb0 = (const float*)d_in[2];
    const float* feW1 = (const float*)d_in[3];
    const float* feb1 = (const float*)d_in[4];
    const float* feW2 = (const float*)d_in[5];
    const float* feb2 = (const float*)d_in[6];
    const float* fnW0 = (const float*)d_in[7];
    const float* fnb0 = (const float*)d_in[8];
    const float* fnW1 = (const float*)d_in[9];
    const float* fnb1 = (const float*)d_in[10];
    float* out = (float*)d_out;

    cudaFuncSetAttribute(mp_main, cudaFuncAttributeMaxDynamicSharedMemorySize, SMEM_SZ);

    pq_kernel<<<512, 256>>>(x, feW0, feb0);
    prep_w<<<352, 256>>>(feW1, feW2);
    prep_vec<<<1, 256>>>(feW0, feb1, feb2);
    mp_main<<<BATCH * NN / 2, THREADS, SMEM_SZ>>>(x);
    node_kernel<<<512, 256>>>(x, fnW0, fnb0, fnW1, fnb1, out);
}

// round 5
// speedup vs baseline: 2.2135x; 1.1397x over previous
#include <cuda_runtime.h>
#include <cuda_fp16.h>
#include <cstdint>

#define BATCH 128
#define NN    64
#define C1    256
#define C2    96
#define PA    264          // A smem pitch in halves (528B -> conflict-free)
#define PB    40           // B smem pitch in halves (80B -> conflict-free)
#define THREADS 256

// ---------------- global scratch ---------------------------------------------
__device__ float  g_P[BATCH * NN * C1];
__device__ float  g_Q[BATCH * NN * C1];
__device__ __half g_B1[8 * 2 * 256 * PB];   // [kchunk][hi|lo][n=256][k=40pad]
__device__ __half g_B2[8 * 2 * 96 * PB];    // [kchunk][hi|lo][n=96][k=40pad]
__device__ float  g_AGG[BATCH * NN * C2];
__device__ float  g_vec[C1 + C1 + 128];     // w0d | b1 | b2

__device__ __forceinline__ float lrelu(float v) { return v > 0.f ? v : 0.2f * v; }

#define CP_ASYNC16(smaddr, gptr) \
    asm volatile("cp.async.cg.shared.global [%0], [%1], 16;" :: "r"(smaddr), "l"(gptr))
#define CP_COMMIT() asm volatile("cp.async.commit_group;")
#define CP_WAIT0()  asm volatile("cp.async.wait_group 0;" ::: "memory")

__device__ __forceinline__ void hmma(float* c, const uint32_t* a, const uint32_t* b) {
    asm volatile(
        "mma.sync.aligned.m16n8k16.row.col.f32.f16.f16.f32 "
        "{%0,%1,%2,%3}, {%4,%5,%6,%7}, {%8,%9}, {%0,%1,%2,%3};"
        : "+f"(c[0]), "+f"(c[1]), "+f"(c[2]), "+f"(c[3])
        : "r"(a[0]), "r"(a[1]), "r"(a[2]), "r"(a[3]), "r"(b[0]), "r"(b[1]));
}

// ---------------- kernel: P/Q precompute (fp32) ------------------------------
__global__ __launch_bounds__(256) void pq_kernel(
    const float* __restrict__ x, const float* __restrict__ W0,
    const float* __restrict__ b0)
{
    __shared__ float xs[16 * 64];
    const int r0 = blockIdx.x * 16;
    const int tid = threadIdx.x;
    ((float4*)xs)[tid] = ((const float4*)(x + (size_t)r0 * 64))[tid];
    __syncthreads();
    const int c = tid;
    float accP[16], accQ[16];
#pragma unroll
    for (int r = 0; r < 16; r++) { accP[r] = 0.f; accQ[r] = 0.f; }
#pragma unroll 4
    for (int f = 0; f < 64; f++) {
        float wp = W0[f * C1 + c];
        float wq = W0[(64 + f) * C1 + c];
#pragma unroll
        for (int r = 0; r < 16; r++) {
            float xv = xs[r * 64 + f];
            accP[r] = fmaf(xv, wp, accP[r]);
            accQ[r] = fmaf(xv, wq, accQ[r]);
        }
    }
    float bias = b0[c];
#pragma unroll
    for (int r = 0; r < 16; r++) {
        g_P[(size_t)(r0 + r) * C1 + c] = accP[r] + bias;
        g_Q[(size_t)(r0 + r) * C1 + c] = accQ[r];
    }
}

// ---------------- kernel: weight fp16 hi/lo split ----------------------------
__global__ __launch_bounds__(256) void prep_w(
    const float* __restrict__ W1, const float* __restrict__ W2)
{
    int idx = blockIdx.x * 256 + threadIdx.x;
    if (idx < 65536) {
        int t = idx >> 13, rem = idx & 8191;
        int n = rem >> 5, k = rem & 31;
        float v = W1[(size_t)(t * 32 + k) * C1 + n];
        __half hi = __float2half_rn(v);
        __half lo = __float2half_rn(v - __half2float(hi));
        size_t base = (size_t)t * 2 * 256 * PB;
        g_B1[base + (size_t)n * PB + k] = hi;
        g_B1[base + 256 * PB + (size_t)n * PB + k] = lo;
    } else if (idx - 65536 < 24576) {
        int p = idx - 65536;
        int t = p / 3072, rem = p % 3072;
        int n = rem >> 5, k = rem & 31;
        float v = W2[(size_t)(t * 32 + k) * C2 + n];
        __half hi = __float2half_rn(v);
        __half lo = __float2half_rn(v - __half2float(hi));
        size_t base = (size_t)t * 2 * 96 * PB;
        g_B2[base + (size_t)n * PB + k] = hi;
        g_B2[base + 96 * PB + (size_t)n * PB + k] = lo;
    }
}

__global__ void prep_vec(const float* __restrict__ W0,
                         const float* __restrict__ b1,
                         const float* __restrict__ b2) {
    int t = threadIdx.x;
    g_vec[t] = W0[128 * C1 + t];
    g_vec[C1 + t] = b1[t];
    if (t < C2) g_vec[2 * C1 + t] = b2[t];
}

// ---------------- main mma.sync kernel ---------------------------------------
#define OFF_AH   0                         // 128 x 264 halves = 67584
#define OFF_AL   67584
#define OFF_B    135168                    // 2 x 40960
#define OFF_PV   217088
#define OFF_W0   219136
#define OFF_B1S  220160
#define OFF_B2S  221184
#define OFF_DIST 221696
#define SMEM_SZ  222208

__global__ void __launch_bounds__(THREADS, 1) mp_main(const float* __restrict__ x)
{
    extern __shared__ __align__(16) unsigned char sm[];
    const unsigned smb = (unsigned)__cvta_generic_to_shared(sm);
    const int tid = threadIdx.x;
    const int w = tid >> 5, lane = tid & 31;
    const int g = lane >> 2, tig = lane & 3;
    const int wm = w & 1, wn = w >> 1;      // 2 m-tiles of 64, 4 n-tiles of 64
    const int b = blockIdx.x >> 5;
    const int i0 = (blockIdx.x & 31) * 2;

    __half* Ah  = (__half*)(sm + OFF_AH);
    __half* Al  = (__half*)(sm + OFF_AL);
    __half* Bsm = (__half*)(sm + OFF_B);
    float* pv   = (float*)(sm + OFF_PV);
    float* w0s  = (float*)(sm + OFF_W0);
    float* b1s  = (float*)(sm + OFF_B1S);
    float* b2s  = (float*)(sm + OFF_B2S);
    float* dst_ = (float*)(sm + OFF_DIST);

    // ---- stage small vectors ----
    {
        pv[tid]       = g_P[(size_t)(b * 64 + i0) * C1 + tid];
        pv[256 + tid] = g_P[(size_t)(b * 64 + i0 + 1) * C1 + tid];
        w0s[tid] = g_vec[tid];
        b1s[tid] = g_vec[C1 + tid];
        if (tid < C2) b2s[tid] = g_vec[2 * C1 + tid];
    }
    // ---- distances (128 rows = 2 i's x 64 j) ----
    if (tid < 128) {
        int isel = tid >> 6, j = tid & 63;
        const float* xi = x + ((size_t)b * 64 + i0 + isel) * 64;
        const float* xj = x + ((size_t)b * 64 + j) * 64;
        float s = 0.f;
#pragma unroll
        for (int f = 0; f < 64; f++) {
            float d = xj[f] - xi[f] + 1e-12f;
            s = fmaf(d, d, s);
        }
        dst_[tid] = sqrtf(s);
    }
    __syncthreads();

    // ---- build h0 fp16 hi/lo: 128 x 256 (each thread: half a row) ----
    {
        int r = tid >> 1, kq = (tid & 1) * 128;
        int isel = r >> 6, j = r & 63;
        float dj = dst_[r];
        const float* pvr = pv + isel * 256;
        const float4* q4 = (const float4*)(g_Q + ((size_t)(b * 64 + j)) * 256);
        __half2* ahp = (__half2*)(Ah + r * PA);
        __half2* alp = (__half2*)(Al + r * PA);
#pragma unroll
        for (int g4 = 0; g4 < 32; g4++) {
            int k = kq + g4 * 4;
            float4 q = q4[k >> 2];
            float v0 = lrelu(pvr[k + 0] + q.x + dj * w0s[k + 0]);
            float v1 = lrelu(pvr[k + 1] + q.y + dj * w0s[k + 1]);
            float v2 = lrelu(pvr[k + 2] + q.z + dj * w0s[k + 2]);
            float v3 = lrelu(pvr[k + 3] + q.w + dj * w0s[k + 3]);
            __half h0 = __float2half_rn(v0), h1 = __float2half_rn(v1);
            __half h2 = __float2half_rn(v2), h3 = __float2half_rn(v3);
            ahp[(k >> 1) + 0] = __halves2half2(h0, h1);
            ahp[(k >> 1) + 1] = __halves2half2(h2, h3);
            alp[(k >> 1) + 0] = __halves2half2(
                __float2half_rn(v0 - __half2float(h0)),
                __float2half_rn(v1 - __half2float(h1)));
            alp[(k >> 1) + 1] = __halves2half2(
                __float2half_rn(v2 - __half2float(h2)),
                __float2half_rn(v3 - __half2float(h3)));
        }
    }

    auto loadB = [&](const __half* gsrc, int dstbuf, int bytes) {
        unsigned sb = smb + OFF_B + dstbuf * 40960;
        const char* gp = (const char*)gsrc;
        for (int q = tid * 16; q < bytes; q += THREADS * 16)
            CP_ASYNC16(sb + q, gp + q);
        CP_COMMIT();
    };

    const int m0 = wm * 64;

    // =================== GEMM1: h1 = lrelu(h0 @ W1 + b1) ====================
    float acc[4][8][4];
#pragma unroll
    for (int mf = 0; mf < 4; mf++)
#pragma unroll
        for (int nf = 0; nf < 8; nf++)
#pragma unroll
            for (int e = 0; e < 4; e++) acc[mf][nf][e] = 0.f;

    loadB(g_B1, 0, 40960);
    for (int tc = 0; tc < 8; tc++) {
        int buf = tc & 1;
        CP_WAIT0();
        __syncthreads();
        if (tc < 7) loadB(g_B1 + (size_t)(tc + 1) * 2 * 256 * PB, buf ^ 1, 40960);
        const __half* Bh = Bsm + buf * 20480;
        const __half* Bl = Bh + 256 * PB;
#pragma unroll
        for (int ks = 0; ks < 2; ks++) {
            int kg = tc * 32 + ks * 16;
            uint32_t ah[4][4], al[4][4];
#pragma unroll
            for (int mf = 0; mf < 4; mf++) {
                const __half* base = Ah + (m0 + mf * 16 + g) * PA + kg + 2 * tig;
                ah[mf][0] = *(const uint32_t*)(base);
                ah[mf][1] = *(const uint32_t*)(base + 8 * PA);
                ah[mf][2] = *(const uint32_t*)(base + 8);
                ah[mf][3] = *(const uint32_t*)(base + 8 * PA + 8);
                const __half* basel = Al + (m0 + mf * 16 + g) * PA + kg + 2 * tig;
                al[mf][0] = *(const uint32_t*)(basel);
                al[mf][1] = *(const uint32_t*)(basel + 8 * PA);
                al[mf][2] = *(const uint32_t*)(basel + 8);
                al[mf][3] = *(const uint32_t*)(basel + 8 * PA + 8);
            }
#pragma unroll
            for (int nf = 0; nf < 8; nf++) {
                int n = wn * 64 + nf * 8 + g;
                int kk = ks * 16 + 2 * tig;
                const __half* bb = Bh + n * PB + kk;
                uint32_t bh[2] = { *(const uint32_t*)bb, *(const uint32_t*)(bb + 8) };
                const __half* bbl = Bl + n * PB + kk;
                uint32_t bl2[2] = { *(const uint32_t*)bbl, *(const uint32_t*)(bbl + 8) };
#pragma unroll
                for (int mf = 0; mf < 4; mf++) hmma(acc[mf][nf], ah[mf], bh);
#pragma unroll
                for (int mf = 0; mf < 4; mf++) hmma(acc[mf][nf], al[mf], bh);
#pragma unroll
                for (int mf = 0; mf < 4; mf++) hmma(acc[mf][nf], ah[mf], bl2);
            }
        }
    }
    __syncthreads();
    loadB(g_B2, 0, 15360);   // prefetch GEMM2 chunk 0

    // ---- h1 epilogue: bias + lrelu, split fp16 hi/lo, overwrite A ----
#pragma unroll
    for (int mf = 0; mf < 4; mf++) {
        int row0 = m0 + mf * 16 + g, row1 = row0 + 8;
#pragma unroll
        for (int nf = 0; nf < 8; nf++) {
            int col = wn * 64 + nf * 8 + 2 * tig;
            float ba = b1s[col], bb = b1s[col + 1];
            float v00 = lrelu(acc[mf][nf][0] + ba), v01 = lrelu(acc[mf][nf][1] + bb);
            float v10 = lrelu(acc[mf][nf][2] + ba), v11 = lrelu(acc[mf][nf][3] + bb);
            __half h00 = __float2half_rn(v00), h01 = __float2half_rn(v01);
            __half h10 = __float2half_rn(v10), h11 = __float2half_rn(v11);
            *(__half2*)(Ah + row0 * PA + col) = __halves2half2(h00, h01);
            *(__half2*)(Ah + row1 * PA + col) = __halves2half2(h10, h11);
            *(__half2*)(Al + row0 * PA + col) = __halves2half2(
                __float2half_rn(v00 - __half2float(h00)),
                __float2half_rn(v01 - __half2float(h01)));
            *(__half2*)(Al + row1 * PA + col) = __halves2half2(
                __float2half_rn(v10 - __half2float(h10)),
                __float2half_rn(v11 - __half2float(h11)));
        }
    }
    __syncthreads();

    // =================== GEMM2: h2 = lrelu(h1 @ W2 + b2) ====================
    float ac2[4][3][4];
#pragma unroll
    for (int mf = 0; mf < 4; mf++)
#pragma unroll
        for (int nf = 0; nf < 3; nf++)
#pragma unroll
            for (int e = 0; e < 4; e++) ac2[mf][nf][e] = 0.f;

    for (int tc = 0; tc < 8; tc++) {
        int buf = tc & 1;
        CP_WAIT0();
        __syncthreads();
        if (tc < 7) loadB(g_B2 + (size_t)(tc + 1) * 2 * 96 * PB, buf ^ 1, 15360);
        const __half* Bh = Bsm + buf * 20480;
        const __half* Bl = Bh + 96 * PB;
#pragma unroll
        for (int ks = 0; ks < 2; ks++) {
            int kg = tc * 32 + ks * 16;
            uint32_t ah[4][4], al[4][4];
#pragma unroll
            for (int mf = 0; mf < 4; mf++) {
                const __half* base = Ah + (m0 + mf * 16 + g) * PA + kg + 2 * tig;
                ah[mf][0] = *(const uint32_t*)(base);
                ah[mf][1] = *(const uint32_t*)(base + 8 * PA);
                ah[mf][2] = *(const uint32_t*)(base + 8);
                ah[mf][3] = *(const uint32_t*)(base + 8 * PA + 8);
                const __half* basel = Al + (m0 + mf * 16 + g) * PA + kg + 2 * tig;
                al[mf][0] = *(const uint32_t*)(basel);
                al[mf][1] = *(const uint32_t*)(basel + 8 * PA);
                al[mf][2] = *(const uint32_t*)(basel + 8);
                al[mf][3] = *(const uint32_t*)(basel + 8 * PA + 8);
            }
#pragma unroll
            for (int nf = 0; nf < 3; nf++) {
                int n = wn * 24 + nf * 8 + g;
                int kk = ks * 16 + 2 * tig;
                const __half* bb = Bh + n * PB + kk;
                uint32_t bh[2] = { *(const uint32_t*)bb, *(const uint32_t*)(bb + 8) };
                const __half* bbl = Bl + n * PB + kk;
                uint32_t bl2[2] = { *(const uint32_t*)bbl, *(const uint32_t*)(bbl + 8) };
#pragma unroll
                for (int mf = 0; mf < 4; mf++) hmma(ac2[mf][nf], ah[mf], bh);
#pragma unroll
                for (int mf = 0; mf < 4; mf++) hmma(ac2[mf][nf], al[mf], bh);
#pragma unroll
                for (int mf = 0; mf < 4; mf++) hmma(ac2[mf][nf], ah[mf], bl2);
            }
        }
    }
    __syncthreads();

    // ---- h2 epilogue: bias + lrelu, stage fp32, then column-sum over j ----
    float* stage = (float*)(sm + OFF_B);   // [128][100]
#pragma unroll
    for (int mf = 0; mf < 4; mf++) {
        int row0 = m0 + mf * 16 + g, row1 = row0 + 8;
#pragma unroll
        for (int nf = 0; nf < 3; nf++) {
            int col = wn * 24 + nf * 8 + 2 * tig;
            float ba = b2s[col], bb = b2s[col + 1];
            stage[row0 * 100 + col]     = lrelu(ac2[mf][nf][0] + ba);
            stage[row0 * 100 + col + 1] = lrelu(ac2[mf][nf][1] + bb);
            stage[row1 * 100 + col]     = lrelu(ac2[mf][nf][2] + ba);
            stage[row1 * 100 + col + 1] = lrelu(ac2[mf][nf][3] + bb);
        }
    }
    __syncthreads();
    if (tid < 192) {
        int isel = tid / 96, c = tid - isel * 96;
        float s = 0.f;
#pragma unroll 8
        for (int r = 0; r < 64; r++) s += stage[(isel * 64 + r) * 100 + c];
        g_AGG[(size_t)(b * 64 + i0 + isel) * C2 + c] = s;
    }
}

// ---------------- node MLP (fp32) --------------------------------------------
__global__ __launch_bounds__(256) void node_kernel(
    const float* __restrict__ x,
    const float* __restrict__ Wn0, const float* __restrict__ bn0,
    const float* __restrict__ Wn1, const float* __restrict__ bn1,
    float* __restrict__ out)
{
    __shared__ float t160[16 * 160];
    __shared__ float zs[16 * 256];
    const int r0 = blockIdx.x * 16;
    const int tid = threadIdx.x;

    for (int idx = tid; idx < 16 * 160; idx += 256) {
        int rr = idx / 160, k = idx - rr * 160;
        t160[idx] = (k < 96) ? g_AGG[(size_t)(r0 + rr) * 96 + k]
                             : x[(size_t)(r0 + rr) * 64 + (k - 96)];
    }
    __syncthreads();
    {
        const int c = tid;
        float acc[16];
        float bb = bn0[c];
#pragma unroll
        for (int r = 0; r < 16; r++) acc[r] = bb;
#pragma unroll 4
        for (int k = 0; k < 160; k++) {
            float wv = Wn0[(size_t)k * 256 + c];
#pragma unroll
            for (int r = 0; r < 16; r++) acc[r] = fmaf(t160[r * 160 + k], wv, acc[r]);
        }
#pragma unroll
        for (int r = 0; r < 16; r++) zs[r * 256 + c] = lrelu(acc[r]);
    }
    __syncthreads();
    for (int pass = 0; pass < 4; pass++) {
        int r = pass * 4 + (tid >> 6), c = tid & 63;
        float a = bn1[c];
#pragma unroll 8
        for (int k = 0; k < 256; k++)
            a = fmaf(zs[r * 256 + k], Wn1[(size_t)k * 64 + c], a);
        out[(size_t)(r0 + r) * 64 + c] = a;
    }
}

// ---------------- launch -----------------------------------------------------
extern "C" void kernel_launch(void* const* d_in, const int* in_sizes, int n_in,
                              void* d_out, int out_size)
{
    const float* x    = (const float*)d_in[0];
    const float* feW0 = (const float*)d_in[1];
    const float* feb0 = (const float*)d_in[2];
    const float* feW1 = (const float*)d_in[3];
    const float* feb1 = (const float*)d_in[4];
    const float* feW2 = (const float*)d_in[5];
    const float* feb2 = (const float*)d_in[6];
    const float* fnW0 = (const float*)d_in[7];
    const float* fnb0 = (const float*)d_in[8];
    const float* fnW1 = (const float*)d_in[9];
    const float* fnb1 = (const float*)d_in[10];
    float* out = (float*)d_out;

    cudaFuncSetAttribute(mp_main, cudaFuncAttributeMaxDynamicSharedMemorySize, SMEM_SZ);

    pq_kernel<<<512, 256>>>(x, feW0, feb0);
    prep_w<<<352, 256>>>(feW1, feW2);
    prep_vec<<<1, 256>>>(feW0, feb1, feb2);
    mp_main<<<BATCH * NN / 2, THREADS, SMEM_SZ>>>(x);
    node_kernel<<<512, 256>>>(x, fnW0, fnb0, fnW1, fnb1, out);
}

// round 7
// speedup vs baseline: 2.2700x; 1.0255x over previous
#include <cuda_runtime.h>
#include <cuda_fp16.h>
#include <cstdint>

#define BATCH 128
#define NN    64
#define C1    256
#define C2    96
#define PA    264          // A smem pitch in halves (528B, conflict-free)
#define PB    20           // B smem pitch in halves (40B; rare 2-way conflicts, accepted)
#define KCH   16           // k-chunk
#define THREADS 128

// ---------------- global scratch ---------------------------------------------
__device__ float  g_P[BATCH * NN * C1];
__device__ float  g_Q[BATCH * NN * C1];
__device__ __half g_B1[16 * 2 * 256 * PB];  // [kchunk16][hi|lo][n=256][k=20pad]
__device__ __half g_B2[16 * 2 * 96 * PB];   // [kchunk16][hi|lo][n=96][k=20pad]
__device__ float  g_AGG[BATCH * NN * C2];
__device__ float  g_vec[C1 + C1 + 128];     // w0d | b1 | b2

__device__ __forceinline__ float lrelu(float v) { return v > 0.f ? v : 0.2f * v; }

#define CP_ASYNC16(smaddr, gptr) \
    asm volatile("cp.async.cg.shared.global [%0], [%1], 16;" :: "r"(smaddr), "l"(gptr))
#define CP_COMMIT() asm volatile("cp.async.commit_group;")
#define CP_WAIT0()  asm volatile("cp.async.wait_group 0;" ::: "memory")

__device__ __forceinline__ void hmma(float* c, const uint32_t* a, const uint32_t* b) {
    asm volatile(
        "mma.sync.aligned.m16n8k16.row.col.f32.f16.f16.f32 "
        "{%0,%1,%2,%3}, {%4,%5,%6,%7}, {%8,%9}, {%0,%1,%2,%3};"
        : "+f"(c[0]), "+f"(c[1]), "+f"(c[2]), "+f"(c[3])
        : "r"(a[0]), "r"(a[1]), "r"(a[2]), "r"(a[3]), "r"(b[0]), "r"(b[1]));
}

// ---------------- kernel: P/Q precompute (fp32) ------------------------------
__global__ __launch_bounds__(256) void pq_kernel(
    const float* __restrict__ x, const float* __restrict__ W0,
    const float* __restrict__ b0)
{
    __shared__ float xs[16 * 64];
    const int r0 = blockIdx.x * 16;
    const int tid = threadIdx.x;
    ((float4*)xs)[tid] = ((const float4*)(x + (size_t)r0 * 64))[tid];
    __syncthreads();
    const int c = tid;
    float accP[16], accQ[16];
#pragma unroll
    for (int r = 0; r < 16; r++) { accP[r] = 0.f; accQ[r] = 0.f; }
#pragma unroll 4
    for (int f = 0; f < 64; f++) {
        float wp = W0[f * C1 + c];
        float wq = W0[(64 + f) * C1 + c];
#pragma unroll
        for (int r = 0; r < 16; r++) {
            float xv = xs[r * 64 + f];
            accP[r] = fmaf(xv, wp, accP[r]);
            accQ[r] = fmaf(xv, wq, accQ[r]);
        }
    }
    float bias = b0[c];
#pragma unroll
    for (int r = 0; r < 16; r++) {
        g_P[(size_t)(r0 + r) * C1 + c] = accP[r] + bias;
        g_Q[(size_t)(r0 + r) * C1 + c] = accQ[r];
    }
}

// ---------------- kernel: weight fp16 hi/lo split (k16 chunks, PB=20) --------
__global__ __launch_bounds__(256) void prep_w(
    const float* __restrict__ W1, const float* __restrict__ W2)
{
    int idx = blockIdx.x * 256 + threadIdx.x;
    if (idx < 65536) {                              // B1: 16 chunks x 256 n x 16 k
        int t = idx >> 12, rem = idx & 4095;
        int n = rem >> 4, k = rem & 15;
        float v = W1[(size_t)(t * KCH + k) * C1 + n];
        __half hi = __float2half_rn(v);
        __half lo = __float2half_rn(v - __half2float(hi));
        size_t base = (size_t)t * 2 * 256 * PB;
        g_B1[base + (size_t)n * PB + k] = hi;
        g_B1[base + 256 * PB + (size_t)n * PB + k] = lo;
    } else if (idx - 65536 < 24576) {               // B2: 16 chunks x 96 n x 16 k
        int p = idx - 65536;
        int t = p / 1536, rem = p % 1536;           // FIXED: 1536 elems per chunk
        int n = rem >> 4, k = rem & 15;
        float v = W2[(size_t)(t * KCH + k) * C2 + n];
        __half hi = __float2half_rn(v);
        __half lo = __float2half_rn(v - __half2float(hi));
        size_t base = (size_t)t * 2 * 96 * PB;
        g_B2[base + (size_t)n * PB + k] = hi;
        g_B2[base + 96 * PB + (size_t)n * PB + k] = lo;
    }
}

__global__ void prep_vec(const float* __restrict__ W0,
                         const float* __restrict__ b1,
                         const float* __restrict__ b2) {
    int t = threadIdx.x;
    g_vec[t] = W0[128 * C1 + t];
    g_vec[C1 + t] = b1[t];
    if (t < C2) g_vec[2 * C1 + t] = b2[t];
}

// ---------------- main mma.sync kernel (1 node / CTA, 2 CTAs per SM) ---------
#define B1_CHUNK_BYTES (2 * 256 * PB * 2)   // 20480
#define B2_CHUNK_BYTES (2 * 96 * PB * 2)    // 7680
#define OFF_AH   0                          // 64 x 264 halves = 33792
#define OFF_AL   33792
#define OFF_B    67584                      // 2 x 20480 = 40960
#define OFF_PV   108544                     // 1024
#define OFF_W0   109568                     // 1024
#define OFF_B1S  110592                     // 1024
#define OFF_B2S  111616                     // 512
#define OFF_DIST 112128                     // 256
#define SMEM_SZ  112384

__global__ void __launch_bounds__(THREADS, 2) mp_main(const float* __restrict__ x)
{
    extern __shared__ __align__(16) unsigned char sm[];
    const unsigned smb = (unsigned)__cvta_generic_to_shared(sm);
    const int tid = threadIdx.x;
    const int w = tid >> 5, lane = tid & 31;
    const int g = lane >> 2, tig = lane & 3;
    const int b = blockIdx.x >> 6;
    const int i = blockIdx.x & 63;

    __half* Ah  = (__half*)(sm + OFF_AH);
    __half* Al  = (__half*)(sm + OFF_AL);
    __half* Bsm = (__half*)(sm + OFF_B);
    float* pv   = (float*)(sm + OFF_PV);
    float* w0s  = (float*)(sm + OFF_W0);
    float* b1s  = (float*)(sm + OFF_B1S);
    float* b2s  = (float*)(sm + OFF_B2S);
    float* dst_ = (float*)(sm + OFF_DIST);

    // ---- stage small vectors ----
    {
        pv[tid]        = g_P[(size_t)(b * 64 + i) * C1 + tid];
        pv[tid + 128]  = g_P[(size_t)(b * 64 + i) * C1 + tid + 128];
        w0s[tid]       = g_vec[tid];
        w0s[tid + 128] = g_vec[tid + 128];
        b1s[tid]       = g_vec[C1 + tid];
        b1s[tid + 128] = g_vec[C1 + tid + 128];
        if (tid < C2) b2s[tid] = g_vec[2 * C1 + tid];
    }
    // ---- distances (64 j) ----
    if (tid < 64) {
        const float* xi = x + ((size_t)b * 64 + i) * 64;
        const float* xj = x + ((size_t)b * 64 + tid) * 64;
        float s = 0.f;
#pragma unroll
        for (int f = 0; f < 64; f++) {
            float d = xj[f] - xi[f] + 1e-12f;
            s = fmaf(d, d, s);
        }
        dst_[tid] = sqrtf(s);
    }
    __syncthreads();

    // ---- build h0 fp16 hi/lo: 64 x 256 (each thread: half a row) ----
    {
        int r = tid >> 1, kq = (tid & 1) * 128;
        float dj = dst_[r];
        const float4* q4 = (const float4*)(g_Q + ((size_t)(b * 64 + r)) * 256);
        __half2* ahp = (__half2*)(Ah + r * PA);
        __half2* alp = (__half2*)(Al + r * PA);
#pragma unroll
        for (int g4 = 0; g4 < 32; g4++) {
            int k = kq + g4 * 4;
            float4 q = q4[k >> 2];
            float v0 = lrelu(pv[k + 0] + q.x + dj * w0s[k + 0]);
            float v1 = lrelu(pv[k + 1] + q.y + dj * w0s[k + 1]);
            float v2 = lrelu(pv[k + 2] + q.z + dj * w0s[k + 2]);
            float v3 = lrelu(pv[k + 3] + q.w + dj * w0s[k + 3]);
            __half h0 = __float2half_rn(v0), h1 = __float2half_rn(v1);
            __half h2 = __float2half_rn(v2), h3 = __float2half_rn(v3);
            ahp[(k >> 1) + 0] = __halves2half2(h0, h1);
            ahp[(k >> 1) + 1] = __halves2half2(h2, h3);
            alp[(k >> 1) + 0] = __halves2half2(
                __float2half_rn(v0 - __half2float(h0)),
                __float2half_rn(v1 - __half2float(h1)));
            alp[(k >> 1) + 1] = __halves2half2(
                __float2half_rn(v2 - __half2float(h2)),
                __float2half_rn(v3 - __half2float(h3)));
        }
    }

    auto loadB = [&](const __half* gsrc, int dstbuf, int bytes) {
        unsigned sb = smb + OFF_B + dstbuf * B1_CHUNK_BYTES;
        const char* gp = (const char*)gsrc;
        for (int q = tid * 16; q < bytes; q += THREADS * 16)
            CP_ASYNC16(sb + q, gp + q);
        CP_COMMIT();
    };

    // =================== GEMM1: h1 = lrelu(h0 @ W1 + b1) ====================
    float acc[4][8][4];
#pragma unroll
    for (int mf = 0; mf < 4; mf++)
#pragma unroll
        for (int nf = 0; nf < 8; nf++)
#pragma unroll
            for (int e = 0; e < 4; e++) acc[mf][nf][e] = 0.f;

    loadB(g_B1, 0, B1_CHUNK_BYTES);
    for (int tc = 0; tc < 16; tc++) {
        int buf = tc & 1;
        CP_WAIT0();
        __syncthreads();
        if (tc < 15) loadB(g_B1 + (size_t)(tc + 1) * 2 * 256 * PB, buf ^ 1, B1_CHUNK_BYTES);
        const __half* Bh = Bsm + buf * (B1_CHUNK_BYTES / 2);
        const __half* Bl = Bh + 256 * PB;
        const int kg = tc * KCH;
        uint32_t ah[4][4], al[4][4];
#pragma unroll
        for (int mf = 0; mf < 4; mf++) {
            const __half* base = Ah + (mf * 16 + g) * PA + kg + 2 * tig;
            ah[mf][0] = *(const uint32_t*)(base);
            ah[mf][1] = *(const uint32_t*)(base + 8 * PA);
            ah[mf][2] = *(const uint32_t*)(base + 8);
            ah[mf][3] = *(const uint32_t*)(base + 8 * PA + 8);
            const __half* basel = Al + (mf * 16 + g) * PA + kg + 2 * tig;
            al[mf][0] = *(const uint32_t*)(basel);
            al[mf][1] = *(const uint32_t*)(basel + 8 * PA);
            al[mf][2] = *(const uint32_t*)(basel + 8);
            al[mf][3] = *(const uint32_t*)(basel + 8 * PA + 8);
        }
#pragma unroll
        for (int nf = 0; nf < 8; nf++) {
            int n = w * 64 + nf * 8 + g;
            const __half* bb = Bh + n * PB + 2 * tig;
            uint32_t bh[2] = { *(const uint32_t*)bb, *(const uint32_t*)(bb + 8) };
            const __half* bbl = Bl + n * PB + 2 * tig;
            uint32_t bl2[2] = { *(const uint32_t*)bbl, *(const uint32_t*)(bbl + 8) };
#pragma unroll
            for (int mf = 0; mf < 4; mf++) hmma(acc[mf][nf], ah[mf], bh);
#pragma unroll
            for (int mf = 0; mf < 4; mf++) hmma(acc[mf][nf], al[mf], bh);
#pragma unroll
            for (int mf = 0; mf < 4; mf++) hmma(acc[mf][nf], ah[mf], bl2);
        }
    }
    __syncthreads();
    loadB(g_B2, 0, B2_CHUNK_BYTES);   // prefetch GEMM2 chunk 0

    // ---- h1 epilogue: bias + lrelu, split fp16 hi/lo, overwrite A ----
#pragma unroll
    for (int mf = 0; mf < 4; mf++) {
        int row0 = mf * 16 + g, row1 = row0 + 8;
#pragma unroll
        for (int nf = 0; nf < 8; nf++) {
            int col = w * 64 + nf * 8 + 2 * tig;
            float ba = b1s[col], bb = b1s[col + 1];
            float v00 = lrelu(acc[mf][nf][0] + ba), v01 = lrelu(acc[mf][nf][1] + bb);
            float v10 = lrelu(acc[mf][nf][2] + ba), v11 = lrelu(acc[mf][nf][3] + bb);
            __half h00 = __float2half_rn(v00), h01 = __float2half_rn(v01);
            __half h10 = __float2half_rn(v10), h11 = __float2half_rn(v11);
            *(__half2*)(Ah + row0 * PA + col) = __halves2half2(h00, h01);
            *(__half2*)(Ah + row1 * PA + col) = __halves2half2(h10, h11);
            *(__half2*)(Al + row0 * PA + col) = __halves2half2(
                __float2half_rn(v00 - __half2float(h00)),
                __float2half_rn(v01 - __half2float(h01)));
            *(__half2*)(Al + row1 * PA + col) = __halves2half2(
                __float2half_rn(v10 - __half2float(h10)),
                __float2half_rn(v11 - __half2float(h11)));
        }
    }
    __syncthreads();

    // =================== GEMM2: h2 = lrelu(h1 @ W2 + b2) ====================
    float ac2[4][3][4];
#pragma unroll
    for (int mf = 0; mf < 4; mf++)
#pragma unroll
        for (int nf = 0; nf < 3; nf++)
#pragma unroll
            for (int e = 0; e < 4; e++) ac2[mf][nf][e] = 0.f;

    for (int tc = 0; tc < 16; tc++) {
        int buf = tc & 1;
        CP_WAIT0();
        __syncthreads();
        if (tc < 15) loadB(g_B2 + (size_t)(tc + 1) * 2 * 96 * PB, buf ^ 1, B2_CHUNK_BYTES);
        const __half* Bh = Bsm + buf * (B1_CHUNK_BYTES / 2);
        const __half* Bl = Bh + 96 * PB;
        const int kg = tc * KCH;
        uint32_t ah[4][4], al[4][4];
#pragma unroll
        for (int mf = 0; mf < 4; mf++) {
            const __half* base = Ah + (mf * 16 + g) * PA + kg + 2 * tig;
            ah[mf][0] = *(const uint32_t*)(base);
            ah[mf][1] = *(const uint32_t*)(base + 8 * PA);
            ah[mf][2] = *(const uint32_t*)(base + 8);
            ah[mf][3] = *(const uint32_t*)(base + 8 * PA + 8);
            const __half* basel = Al + (mf * 16 + g) * PA + kg + 2 * tig;
            al[mf][0] = *(const uint32_t*)(basel);
            al[mf][1] = *(const uint32_t*)(basel + 8 * PA);
            al[mf][2] = *(const uint32_t*)(basel + 8);
            al[mf][3] = *(const uint32_t*)(basel + 8 * PA + 8);
        }
#pragma unroll
        for (int nf = 0; nf < 3; nf++) {
            int n = w * 24 + nf * 8 + g;
            const __half* bb = Bh + n * PB + 2 * tig;
            uint32_t bh[2] = { *(const uint32_t*)bb, *(const uint32_t*)(bb + 8) };
            const __half* bbl = Bl + n * PB + 2 * tig;
            uint32_t bl2[2] = { *(const uint32_t*)bbl, *(const uint32_t*)(bbl + 8) };
#pragma unroll
            for (int mf = 0; mf < 4; mf++) hmma(ac2[mf][nf], ah[mf], bh);
#pragma unroll
            for (int mf = 0; mf < 4; mf++) hmma(ac2[mf][nf], al[mf], bh);
#pragma unroll
            for (int mf = 0; mf < 4; mf++) hmma(ac2[mf][nf], ah[mf], bl2);
        }
    }
    __syncthreads();

    // ---- h2 epilogue: bias + lrelu, stage fp32 [64][100], column-sum over j ----
    float* stage = (float*)(sm + OFF_B);
#pragma unroll
    for (int mf = 0; mf < 4; mf++) {
        int row0 = mf * 16 + g, row1 = row0 + 8;
#pragma unroll
        for (int nf = 0; nf < 3; nf++) {
            int col = w * 24 + nf * 8 + 2 * tig;
            float ba = b2s[col], bb = b2s[col + 1];
            stage[row0 * 100 + col]     = lrelu(ac2[mf][nf][0] + ba);
            stage[row0 * 100 + col + 1] = lrelu(ac2[mf][nf][1] + bb);
            stage[row1 * 100 + col]     = lrelu(ac2[mf][nf][2] + ba);
            stage[row1 * 100 + col + 1] = lrelu(ac2[mf][nf][3] + bb);
        }
    }
    __syncthreads();
    if (tid < 96) {
        float s = 0.f;
#pragma unroll 8
        for (int r = 0; r < 64; r++) s += stage[r * 100 + tid];
        g_AGG[(size_t)(b * 64 + i) * C2 + tid] = s;
    }
}

// ---------------- node MLP (fp32) --------------------------------------------
__global__ __launch_bounds__(256) void node_kernel(
    const float* __restrict__ x,
    const float* __restrict__ Wn0, const float* __restrict__ bn0,
    const float* __restrict__ Wn1, const float* __restrict__ bn1,
    float* __restrict__ out)
{
    __shared__ float t160[16 * 160];
    __shared__ float zs[16 * 256];
    const int r0 = blockIdx.x * 16;
    const int tid = threadIdx.x;

    for (int idx = tid; idx < 16 * 160; idx += 256) {
        int rr = idx / 160, k = idx - rr * 160;
        t160[idx] = (k < 96) ? g_AGG[(size_t)(r0 + rr) * 96 + k]
                             : x[(size_t)(r0 + rr) * 64 + (k - 96)];
    }
    __syncthreads();
    {
        const int c = tid;
        float acc[16];
        float bb = bn0[c];
#pragma unroll
        for (int r = 0; r < 16; r++) acc[r] = bb;
#pragma unroll 4
        for (int k = 0; k < 160; k++) {
            float wv = Wn0[(size_t)k * 256 + c];
#pragma unroll
            for (int r = 0; r < 16; r++) acc[r] = fmaf(t160[r * 160 + k], wv, acc[r]);
        }
#pragma unroll
        for (int r = 0; r < 16; r++) zs[r * 256 + c] = lrelu(acc[r]);
    }
    __syncthreads();
    for (int pass = 0; pass < 4; pass++) {
        int r = pass * 4 + (tid >> 6), c = tid & 63;
        float a = bn1[c];
#pragma unroll 8
        for (int k = 0; k < 256; k++)
            a = fmaf(zs[r * 256 + k], Wn1[(size_t)k * 64 + c], a);
        out[(size_t)(r0 + r) * 64 + c] = a;
    }
}

// ---------------- launch -----------------------------------------------------
extern "C" void kernel_launch(void* const* d_in, const int* in_sizes, int n_in,
                              void* d_out, int out_size)
{
    const float* x    = (const float*)d_in[0];
    const float* feW0 = (const float*)d_in[1];
    const float* feb0 = (const float*)d_in[2];
    const float* feW1 = (const float*)d_in[3];
    const float* feb1 = (const float*)d_in[4];
    const float* feW2 = (const float*)d_in[5];
    const float* feb2 = (const float*)d_in[6];
    const float* fnW0 = (const float*)d_in[7];
    const float* fnb0 = (const float*)d_in[8];
    const float* fnW1 = (const float*)d_in[9];
    const float* fnb1 = (const float*)d_in[10];
    float* out = (float*)d_out;

    cudaFuncSetAttribute(mp_main, cudaFuncAttributeMaxDynamicSharedMemorySize, SMEM_SZ);

    pq_kernel<<<512, 256>>>(x, feW0, feb0);
    prep_w<<<352, 256>>>(feW1, feW2);
    prep_vec<<<1, 256>>>(feW0, feb1, feb2);
    mp_main<<<BATCH * NN, THREADS, SMEM_SZ>>>(x);
    node_kernel<<<512, 256>>>(x, fnW0, fnb0, fnW1, fnb1, out);
}

// round 8
// speedup vs baseline: 2.8636x; 1.2615x over previous
#include <cuda_runtime.h>
#include <cuda_fp16.h>
#include <cstdint>

#define BATCH 128
#define NN    64
#define C1    256
#define C2    96
#define PA    264          // A smem pitch in halves (528B, conflict-free)
#define PB    40           // B smem pitch in halves (80B, conflict-free)
#define KCH   32           // k-chunk
#define THREADS 128

// ---------------- global scratch ---------------------------------------------
__device__ float  g_P[BATCH * NN * C1];
__device__ float  g_Q[BATCH * NN * C1];
__device__ __half g_B1[8 * 256 * PB];       // [kchunk32][n=256][k=40pad]  (fp16, no lo term)
__device__ __half g_B2[8 * 96 * PB];        // [kchunk32][n=96][k=40pad]
__device__ float  g_AGG[BATCH * NN * C2];
__device__ float  g_vec[C1 + C1 + 128];     // w0d | b1 | b2

__device__ __forceinline__ float lrelu(float v) { return v > 0.f ? v : 0.2f * v; }

#define CP_ASYNC16(smaddr, gptr) \
    asm volatile("cp.async.cg.shared.global [%0], [%1], 16;" :: "r"(smaddr), "l"(gptr))
#define CP_COMMIT() asm volatile("cp.async.commit_group;")
#define CP_WAIT0()  asm volatile("cp.async.wait_group 0;" ::: "memory")

__device__ __forceinline__ void hmma(float* c, const uint32_t* a, const uint32_t* b) {
    asm volatile(
        "mma.sync.aligned.m16n8k16.row.col.f32.f16.f16.f32 "
        "{%0,%1,%2,%3}, {%4,%5,%6,%7}, {%8,%9}, {%0,%1,%2,%3};"
        : "+f"(c[0]), "+f"(c[1]), "+f"(c[2]), "+f"(c[3])
        : "r"(a[0]), "r"(a[1]), "r"(a[2]), "r"(a[3]), "r"(b[0]), "r"(b[1]));
}

// ---------------- kernel: P/Q precompute (fp32) ------------------------------
__global__ __launch_bounds__(256) void pq_kernel(
    const float* __restrict__ x, const float* __restrict__ W0,
    const float* __restrict__ b0)
{
    __shared__ float xs[16 * 64];
    const int r0 = blockIdx.x * 16;
    const int tid = threadIdx.x;
    ((float4*)xs)[tid] = ((const float4*)(x + (size_t)r0 * 64))[tid];
    __syncthreads();
    const int c = tid;
    float accP[16], accQ[16];
#pragma unroll
    for (int r = 0; r < 16; r++) { accP[r] = 0.f; accQ[r] = 0.f; }
#pragma unroll 4
    for (int f = 0; f < 64; f++) {
        float wp = W0[f * C1 + c];
        float wq = W0[(64 + f) * C1 + c];
#pragma unroll
        for (int r = 0; r < 16; r++) {
            float xv = xs[r * 64 + f];
            accP[r] = fmaf(xv, wp, accP[r]);
            accQ[r] = fmaf(xv, wq, accQ[r]);
        }
    }
    float bias = b0[c];
#pragma unroll
    for (int r = 0; r < 16; r++) {
        g_P[(size_t)(r0 + r) * C1 + c] = accP[r] + bias;
        g_Q[(size_t)(r0 + r) * C1 + c] = accQ[r];
    }
}

// ---------------- kernel: weight fp16 pack (k32 chunks, PB=40) ---------------
__global__ __launch_bounds__(256) void prep_w(
    const float* __restrict__ W1, const float* __restrict__ W2)
{
    int idx = blockIdx.x * 256 + threadIdx.x;
    if (idx < 65536) {                              // B1: 8 chunks x 256 n x 32 k
        int t = idx >> 13, rem = idx & 8191;
        int n = rem >> 5, k = rem & 31;
        float v = W1[(size_t)(t * KCH + k) * C1 + n];
        g_B1[(size_t)t * 256 * PB + (size_t)n * PB + k] = __float2half_rn(v);
    } else if (idx - 65536 < 24576) {               // B2: 8 chunks x 96 n x 32 k
        int p = idx - 65536;
        int t = p / 3072, rem = p % 3072;
        int n = rem >> 5, k = rem & 31;
        float v = W2[(size_t)(t * KCH + k) * C2 + n];
        g_B2[(size_t)t * 96 * PB + (size_t)n * PB + k] = __float2half_rn(v);
    }
}

__global__ void prep_vec(const float* __restrict__ W0,
                         const float* __restrict__ b1,
                         const float* __restrict__ b2) {
    int t = threadIdx.x;
    g_vec[t] = W0[128 * C1 + t];
    g_vec[C1 + t] = b1[t];
    if (t < C2) g_vec[2 * C1 + t] = b2[t];
}

// ---------------- main mma.sync kernel (1 node / CTA, 2 CTAs per SM) ---------
#define B1_CHUNK_HALVES (256 * PB)          // 10240 halves = 20480 B
#define B1_CHUNK_BYTES  (B1_CHUNK_HALVES * 2)
#define B2_CHUNK_HALVES (96 * PB)           // 3840 halves = 7680 B
#define B2_CHUNK_BYTES  (B2_CHUNK_HALVES * 2)
#define OFF_AH   0                          // 64 x 264 halves = 33792
#define OFF_AL   33792
#define OFF_B    67584                      // 2 x 20480 = 40960
#define OFF_PV   108544                     // 1024
#define OFF_W0   109568                     // 1024
#define OFF_B1S  110592                     // 1024
#define OFF_B2S  111616                     // 512
#define OFF_DIST 112128                     // 256
#define SMEM_SZ  112384

__global__ void __launch_bounds__(THREADS, 2) mp_main(const float* __restrict__ x)
{
    extern __shared__ __align__(16) unsigned char sm[];
    const unsigned smb = (unsigned)__cvta_generic_to_shared(sm);
    const int tid = threadIdx.x;
    const int w = tid >> 5, lane = tid & 31;
    const int g = lane >> 2, tig = lane & 3;
    const int b = blockIdx.x >> 6;
    const int i = blockIdx.x & 63;

    __half* Ah  = (__half*)(sm + OFF_AH);
    __half* Al  = (__half*)(sm + OFF_AL);
    __half* Bsm = (__half*)(sm + OFF_B);
    float* pv   = (float*)(sm + OFF_PV);
    float* w0s  = (float*)(sm + OFF_W0);
    float* b1s  = (float*)(sm + OFF_B1S);
    float* b2s  = (float*)(sm + OFF_B2S);
    float* dst_ = (float*)(sm + OFF_DIST);

    // ---- stage small vectors ----
    {
        pv[tid]        = g_P[(size_t)(b * 64 + i) * C1 + tid];
        pv[tid + 128]  = g_P[(size_t)(b * 64 + i) * C1 + tid + 128];
        w0s[tid]       = g_vec[tid];
        w0s[tid + 128] = g_vec[tid + 128];
        b1s[tid]       = g_vec[C1 + tid];
        b1s[tid + 128] = g_vec[C1 + tid + 128];
        if (tid < C2) b2s[tid] = g_vec[2 * C1 + tid];
    }
    // ---- distances (64 j) ----
    if (tid < 64) {
        const float* xi = x + ((size_t)b * 64 + i) * 64;
        const float* xj = x + ((size_t)b * 64 + tid) * 64;
        float s = 0.f;
#pragma unroll
        for (int f = 0; f < 64; f++) {
            float d = xj[f] - xi[f] + 1e-12f;
            s = fmaf(d, d, s);
        }
        dst_[tid] = sqrtf(s);
    }
    __syncthreads();

    // ---- build h0 fp16 hi/lo: 64 x 256 (each thread: half a row) ----
    {
        int r = tid >> 1, kq = (tid & 1) * 128;
        float dj = dst_[r];
        const float4* q4 = (const float4*)(g_Q + ((size_t)(b * 64 + r)) * 256);
        __half2* ahp = (__half2*)(Ah + r * PA);
        __half2* alp = (__half2*)(Al + r * PA);
#pragma unroll
        for (int g4 = 0; g4 < 32; g4++) {
            int k = kq + g4 * 4;
            float4 q = q4[k >> 2];
            float v0 = lrelu(pv[k + 0] + q.x + dj * w0s[k + 0]);
            float v1 = lrelu(pv[k + 1] + q.y + dj * w0s[k + 1]);
            float v2 = lrelu(pv[k + 2] + q.z + dj * w0s[k + 2]);
            float v3 = lrelu(pv[k + 3] + q.w + dj * w0s[k + 3]);
            __half h0 = __float2half_rn(v0), h1 = __float2half_rn(v1);
            __half h2 = __float2half_rn(v2), h3 = __float2half_rn(v3);
            ahp[(k >> 1) + 0] = __halves2half2(h0, h1);
            ahp[(k >> 1) + 1] = __halves2half2(h2, h3);
            alp[(k >> 1) + 0] = __halves2half2(
                __float2half_rn(v0 - __half2float(h0)),
                __float2half_rn(v1 - __half2float(h1)));
            alp[(k >> 1) + 1] = __halves2half2(
                __float2half_rn(v2 - __half2float(h2)),
                __float2half_rn(v3 - __half2float(h3)));
        }
    }

    auto loadB = [&](const __half* gsrc, int dstbuf, int bytes) {
        unsigned sb = smb + OFF_B + dstbuf * B1_CHUNK_BYTES;
        const char* gp = (const char*)gsrc;
        for (int q = tid * 16; q < bytes; q += THREADS * 16)
            CP_ASYNC16(sb + q, gp + q);
        CP_COMMIT();
    };

    // =================== GEMM1: h1 = lrelu(h0 @ W1 + b1) ====================
    float acc[4][8][4];
#pragma unroll
    for (int mf = 0; mf < 4; mf++)
#pragma unroll
        for (int nf = 0; nf < 8; nf++)
#pragma unroll
            for (int e = 0; e < 4; e++) acc[mf][nf][e] = 0.f;

    loadB(g_B1, 0, B1_CHUNK_BYTES);
    for (int tc = 0; tc < 8; tc++) {
        int buf = tc & 1;
        CP_WAIT0();
        __syncthreads();
        if (tc < 7) loadB(g_B1 + (size_t)(tc + 1) * B1_CHUNK_HALVES, buf ^ 1, B1_CHUNK_BYTES);
        const __half* Bh = Bsm + buf * B1_CHUNK_HALVES;
#pragma unroll
        for (int grp = 0; grp < 2; grp++) {
            const int kg = tc * KCH + grp * 16;
            uint32_t ah[4][4], al[4][4];
#pragma unroll
            for (int mf = 0; mf < 4; mf++) {
                const __half* base = Ah + (mf * 16 + g) * PA + kg + 2 * tig;
                ah[mf][0] = *(const uint32_t*)(base);
                ah[mf][1] = *(const uint32_t*)(base + 8 * PA);
                ah[mf][2] = *(const uint32_t*)(base + 8);
                ah[mf][3] = *(const uint32_t*)(base + 8 * PA + 8);
                const __half* basel = Al + (mf * 16 + g) * PA + kg + 2 * tig;
                al[mf][0] = *(const uint32_t*)(basel);
                al[mf][1] = *(const uint32_t*)(basel + 8 * PA);
                al[mf][2] = *(const uint32_t*)(basel + 8);
                al[mf][3] = *(const uint32_t*)(basel + 8 * PA + 8);
            }
#pragma unroll
            for (int nf = 0; nf < 8; nf++) {
                int n = w * 64 + nf * 8 + g;
                const __half* bb = Bh + n * PB + grp * 16 + 2 * tig;
                uint32_t bh[2] = { *(const uint32_t*)bb, *(const uint32_t*)(bb + 8) };
#pragma unroll
                for (int mf = 0; mf < 4; mf++) hmma(acc[mf][nf], ah[mf], bh);
#pragma unroll
                for (int mf = 0; mf < 4; mf++) hmma(acc[mf][nf], al[mf], bh);
            }
        }
    }
    __syncthreads();
    loadB(g_B2, 0, B2_CHUNK_BYTES);   // prefetch GEMM2 chunk 0

    // ---- h1 epilogue: bias + lrelu, split fp16 hi/lo, overwrite A ----
#pragma unroll
    for (int mf = 0; mf < 4; mf++) {
        int row0 = mf * 16 + g, row1 = row0 + 8;
#pragma unroll
        for (int nf = 0; nf < 8; nf++) {
            int col = w * 64 + nf * 8 + 2 * tig;
            float ba = b1s[col], bb = b1s[col + 1];
            float v00 = lrelu(acc[mf][nf][0] + ba), v01 = lrelu(acc[mf][nf][1] + bb);
            float v10 = lrelu(acc[mf][nf][2] + ba), v11 = lrelu(acc[mf][nf][3] + bb);
            __half h00 = __float2half_rn(v00), h01 = __float2half_rn(v01);
            __half h10 = __float2half_rn(v10), h11 = __float2half_rn(v11);
            *(__half2*)(Ah + row0 * PA + col) = __halves2half2(h00, h01);
            *(__half2*)(Ah + row1 * PA + col) = __halves2half2(h10, h11);
            *(__half2*)(Al + row0 * PA + col) = __halves2half2(
                __float2half_rn(v00 - __half2float(h00)),
                __float2half_rn(v01 - __half2float(h01)));
            *(__half2*)(Al + row1 * PA + col) = __halves2half2(
                __float2half_rn(v10 - __half2float(h10)),
                __float2half_rn(v11 - __half2float(h11)));
        }
    }
    __syncthreads();

    // =================== GEMM2: h2 = lrelu(h1 @ W2 + b2) ====================
    float ac2[4][3][4];
#pragma unroll
    for (int mf = 0; mf < 4; mf++)
#pragma unroll
        for (int nf = 0; nf < 3; nf++)
#pragma unroll
            for (int e = 0; e < 4; e++) ac2[mf][nf][e] = 0.f;

    for (int tc = 0; tc < 8; tc++) {
        int buf = tc & 1;
        CP_WAIT0();
        __syncthreads();
        if (tc < 7) loadB(g_B2 + (size_t)(tc + 1) * B2_CHUNK_HALVES, buf ^ 1, B2_CHUNK_BYTES);
        const __half* Bh = Bsm + buf * B1_CHUNK_HALVES;
#pragma unroll
        for (int grp = 0; grp < 2; grp++) {
            const int kg = tc * KCH + grp * 16;
            uint32_t ah[4][4], al[4][4];
#pragma unroll
            for (int mf = 0; mf < 4; mf++) {
                const __half* base = Ah + (mf * 16 + g) * PA + kg + 2 * tig;
                ah[mf][0] = *(const uint32_t*)(base);
                ah[mf][1] = *(const uint32_t*)(base + 8 * PA);
                ah[mf][2] = *(const uint32_t*)(base + 8);
                ah[mf][3] = *(const uint32_t*)(base + 8 * PA + 8);
                const __half* basel = Al + (mf * 16 + g) * PA + kg + 2 * tig;
                al[mf][0] = *(const uint32_t*)(basel);
                al[mf][1] = *(const uint32_t*)(basel + 8 * PA);
                al[mf][2] = *(const uint32_t*)(basel + 8);
                al[mf][3] = *(const uint32_t*)(basel + 8 * PA + 8);
            }
#pragma unroll
            for (int nf = 0; nf < 3; nf++) {
                int n = w * 24 + nf * 8 + g;
                const __half* bb = Bh + n * PB + grp * 16 + 2 * tig;
                uint32_t bh[2] = { *(const uint32_t*)bb, *(const uint32_t*)(bb + 8) };
#pragma unroll
                for (int mf = 0; mf < 4; mf++) hmma(ac2[mf][nf], ah[mf], bh);
#pragma unroll
                for (int mf = 0; mf < 4; mf++) hmma(ac2[mf][nf], al[mf], bh);
            }
        }
    }
    __syncthreads();

    // ---- h2 epilogue: bias + lrelu, stage fp32 [64][100], column-sum over j ----
    float* stage = (float*)(sm + OFF_B);
#pragma unroll
    for (int mf = 0; mf < 4; mf++) {
        int row0 = mf * 16 + g, row1 = row0 + 8;
#pragma unroll
        for (int nf = 0; nf < 3; nf++) {
            int col = w * 24 + nf * 8 + 2 * tig;
            float ba = b2s[col], bb = b2s[col + 1];
            stage[row0 * 100 + col]     = lrelu(ac2[mf][nf][0] + ba);
            stage[row0 * 100 + col + 1] = lrelu(ac2[mf][nf][1] + bb);
            stage[row1 * 100 + col]     = lrelu(ac2[mf][nf][2] + ba);
            stage[row1 * 100 + col + 1] = lrelu(ac2[mf][nf][3] + bb);
        }
    }
    __syncthreads();
    if (tid < 96) {
        float s = 0.f;
#pragma unroll 8
        for (int r = 0; r < 64; r++) s += stage[r * 100 + tid];
        g_AGG[(size_t)(b * 64 + i) * C2 + tid] = s;
    }
}

// ---------------- node MLP (fp32) --------------------------------------------
__global__ __launch_bounds__(256) void node_kernel(
    const float* __restrict__ x,
    const float* __restrict__ Wn0, const float* __restrict__ bn0,
    const float* __restrict__ Wn1, const float* __restrict__ bn1,
    float* __restrict__ out)
{
    __shared__ float t160[16 * 160];
    __shared__ float zs[16 * 256];
    const int r0 = blockIdx.x * 16;
    const int tid = threadIdx.x;

    for (int idx = tid; idx < 16 * 160; idx += 256) {
        int rr = idx / 160, k = idx - rr * 160;
        t160[idx] = (k < 96) ? g_AGG[(size_t)(r0 + rr) * 96 + k]
                             : x[(size_t)(r0 + rr) * 64 + (k - 96)];
    }
    __syncthreads();
    {
        const int c = tid;
        float acc[16];
        float bb = bn0[c];
#pragma unroll
        for (int r = 0; r < 16; r++) acc[r] = bb;
#pragma unroll 4
        for (int k = 0; k < 160; k++) {
            float wv = Wn0[(size_t)k * 256 + c];
#pragma unroll
            for (int r = 0; r < 16; r++) acc[r] = fmaf(t160[r * 160 + k], wv, acc[r]);
        }
#pragma unroll
        for (int r = 0; r < 16; r++) zs[r * 256 + c] = lrelu(acc[r]);
    }
    __syncthreads();
    for (int pass = 0; pass < 4; pass++) {
        int r = pass * 4 + (tid >> 6), c = tid & 63;
        float a = bn1[c];
#pragma unroll 8
        for (int k = 0; k < 256; k++)
            a = fmaf(zs[r * 256 + k], Wn1[(size_t)k * 64 + c], a);
        out[(size_t)(r0 + r) * 64 + c] = a;
    }
}

// ---------------- launch -----------------------------------------------------
extern "C" void kernel_launch(void* const* d_in, const int* in_sizes, int n_in,
                              void* d_out, int out_size)
{
    const float* x    = (const float*)d_in[0];
    const float* feW0 = (const float*)d_in[1];
    const float* feb0 = (const float*)d_in[2];
    const float* feW1 = (const float*)d_in[3];
    const float* feb1 = (const float*)d_in[4];
    const float* feW2 = (const float*)d_in[5];
    const float* feb2 = (const float*)d_in[6];
    const float* fnW0 = (const float*)d_in[7];
    const float* fnb0 = (const float*)d_in[8];
    const float* fnW1 = (const float*)d_in[9];
    const float* fnb1 = (const float*)d_in[10];
    float* out = (float*)d_out;

    cudaFuncSetAttribute(mp_main, cudaFuncAttributeMaxDynamicSharedMemorySize, SMEM_SZ);

    pq_kernel<<<512, 256>>>(x, feW0, feb0);
    prep_w<<<352, 256>>>(feW1, feW2);
    prep_vec<<<1, 256>>>(feW0, feb1, feb2);
    mp_main<<<BATCH * NN, THREADS, SMEM_SZ>>>(x);
    node_kernel<<<512, 256>>>(x, fnW0, fnb0, fnW1, fnb1, out);
}

// round 10
// speedup vs baseline: 2.9077x; 1.0154x over previous
#include <cuda_runtime.h>
#include <cuda_fp16.h>
#include <cstdint>

#define BATCH 128
#define NN    64
#define C1    256
#define C2    96
#define PA    264          // A smem pitch in halves (528B, 16B-aligned, conflict-free)
#define PB    40           // B smem pitch in halves (80B, 16B-aligned)
#define KCH   32           // k-chunk
#define THREADS 128

// ---------------- global scratch ---------------------------------------------
__device__ float  g_P[BATCH * NN * C1];
__device__ float  g_Q[BATCH * NN * C1];
__device__ __half g_B1[8 * 256 * PB];       // [kchunk32][n=256][k=40pad]
__device__ __half g_B2[8 * 96 * PB];        // [kchunk32][n=96][k=40pad]
__device__ float  g_AGG[BATCH * NN * C2];
__device__ float  g_vec[C1 + C1 + 128];     // w0d | b1 | b2

__device__ __forceinline__ float lrelu(float v) { return v > 0.f ? v : 0.2f * v; }

#define CP_ASYNC16(smaddr, gptr) \
    asm volatile("cp.async.cg.shared.global [%0], [%1], 16;" :: "r"(smaddr), "l"(gptr))
#define CP_COMMIT() asm volatile("cp.async.commit_group;")
#define CP_WAIT0()  asm volatile("cp.async.wait_group 0;" ::: "memory")

__device__ __forceinline__ void hmma(float* c, const uint32_t* a, const uint32_t* b) {
    asm volatile(
        "mma.sync.aligned.m16n8k16.row.col.f32.f16.f16.f32 "
        "{%0,%1,%2,%3}, {%4,%5,%6,%7}, {%8,%9}, {%0,%1,%2,%3};"
        : "+f"(c[0]), "+f"(c[1]), "+f"(c[2]), "+f"(c[3])
        : "r"(a[0]), "r"(a[1]), "r"(a[2]), "r"(a[3]), "r"(b[0]), "r"(b[1]));
}

#define LDSM4(R0, R1, R2, R3, ADDR) \
    asm volatile("ldmatrix.sync.aligned.m8n8.x4.shared.b16 {%0,%1,%2,%3}, [%4];" \
        : "=r"(R0), "=r"(R1), "=r"(R2), "=r"(R3) : "r"(ADDR))
#define LDSM2(R0, R1, ADDR) \
    asm volatile("ldmatrix.sync.aligned.m8n8.x2.shared.b16 {%0,%1}, [%2];" \
        : "=r"(R0), "=r"(R1) : "r"(ADDR))

// ---------------- kernel: P/Q precompute (fp32) ------------------------------
__global__ __launch_bounds__(256) void pq_kernel(
    const float* __restrict__ x, const float* __restrict__ W0,
    const float* __restrict__ b0)
{
    __shared__ float xs[16 * 64];
    const int r0 = blockIdx.x * 16;
    const int tid = threadIdx.x;
    ((float4*)xs)[tid] = ((const float4*)(x + (size_t)r0 * 64))[tid];
    __syncthreads();
    const int c = tid;
    float accP[16], accQ[16];
#pragma unroll
    for (int r = 0; r < 16; r++) { accP[r] = 0.f; accQ[r] = 0.f; }
#pragma unroll 4
    for (int f = 0; f < 64; f++) {
        float wp = W0[f * C1 + c];
        float wq = W0[(64 + f) * C1 + c];
#pragma unroll
        for (int r = 0; r < 16; r++) {
            float xv = xs[r * 64 + f];
            accP[r] = fmaf(xv, wp, accP[r]);
            accQ[r] = fmaf(xv, wq, accQ[r]);
        }
    }
    float bias = b0[c];
#pragma unroll
    for (int r = 0; r < 16; r++) {
        g_P[(size_t)(r0 + r) * C1 + c] = accP[r] + bias;
        g_Q[(size_t)(r0 + r) * C1 + c] = accQ[r];
    }
}

// ---------------- kernel: weight fp16 pack (k32 chunks, PB=40) ---------------
__global__ __launch_bounds__(256) void prep_w(
    const float* __restrict__ W1, const float* __restrict__ W2)
{
    int idx = blockIdx.x * 256 + threadIdx.x;
    if (idx < 65536) {                              // B1: 8 chunks x 256 n x 32 k
        int t = idx >> 13, rem = idx & 8191;
        int n = rem >> 5, k = rem & 31;
        float v = W1[(size_t)(t * KCH + k) * C1 + n];
        g_B1[(size_t)t * 256 * PB + (size_t)n * PB + k] = __float2half_rn(v);
    } else if (idx - 65536 < 24576) {               // B2: 8 chunks x 96 n x 32 k
        int p = idx - 65536;
        int t = p / 3072, rem = p % 3072;
        int n = rem >> 5, k = rem & 31;
        float v = W2[(size_t)(t * KCH + k) * C2 + n];
        g_B2[(size_t)t * 96 * PB + (size_t)n * PB + k] = __float2half_rn(v);
    }
}

__global__ void prep_vec(const float* __restrict__ W0,
                         const float* __restrict__ b1,
                         const float* __restrict__ b2) {
    int t = threadIdx.x;
    g_vec[t] = W0[128 * C1 + t];
    g_vec[C1 + t] = b1[t];
    if (t < C2) g_vec[2 * C1 + t] = b2[t];
}

// ---------------- main mma.sync kernel (1 node / CTA, 2 CTAs per SM) ---------
#define B1_CHUNK_HALVES (256 * PB)
#define B1_CHUNK_BYTES  (B1_CHUNK_HALVES * 2)   // 20480
#define B2_CHUNK_HALVES (96 * PB)
#define B2_CHUNK_BYTES  (B2_CHUNK_HALVES * 2)   // 7680
#define OFF_AH   0                          // 64 x 264 halves = 33792
#define OFF_AL   33792
#define OFF_B    67584                      // 2 x 20480 = 40960
#define OFF_PV   108544
#define OFF_W0   109568
#define OFF_B1S  110592
#define OFF_B2S  111616
#define OFF_DIST 112128
#define SMEM_SZ  112384

__global__ void __launch_bounds__(THREADS, 2) mp_main(const float* __restrict__ x)
{
    extern __shared__ __align__(16) unsigned char sm[];
    const unsigned smb = (unsigned)__cvta_generic_to_shared(sm);
    const int tid = threadIdx.x;
    const int w = tid >> 5, lane = tid & 31;
    const int b = blockIdx.x >> 6;
    const int i = blockIdx.x & 63;

    __half* Ah  = (__half*)(sm + OFF_AH);
    __half* Al  = (__half*)(sm + OFF_AL);
    float* pv   = (float*)(sm + OFF_PV);
    float* w0s  = (float*)(sm + OFF_W0);
    float* b1s  = (float*)(sm + OFF_B1S);
    float* b2s  = (float*)(sm + OFF_B2S);
    float* dst_ = (float*)(sm + OFF_DIST);

    auto loadB = [&](const __half* gsrc, int dstbuf, int bytes) {
        unsigned sb = smb + OFF_B + dstbuf * B1_CHUNK_BYTES;
        const char* gp = (const char*)gsrc;
        for (int q = tid * 16; q < bytes; q += THREADS * 16)
            CP_ASYNC16(sb + q, gp + q);
        CP_COMMIT();
    };

    // issue first weight-chunk load immediately (overlaps with h0 build)
    loadB(g_B1, 0, B1_CHUNK_BYTES);

    // ---- stage small vectors ----
    {
        pv[tid]        = g_P[(size_t)(b * 64 + i) * C1 + tid];
        pv[tid + 128]  = g_P[(size_t)(b * 64 + i) * C1 + tid + 128];
        w0s[tid]       = g_vec[tid];
        w0s[tid + 128] = g_vec[tid + 128];
        b1s[tid]       = g_vec[C1 + tid];
        b1s[tid + 128] = g_vec[C1 + tid + 128];
        if (tid < C2) b2s[tid] = g_vec[2 * C1 + tid];
    }
    // ---- distances (64 j) ----
    if (tid < 64) {
        const float* xi = x + ((size_t)b * 64 + i) * 64;
        const float* xj = x + ((size_t)b * 64 + tid) * 64;
        float s = 0.f;
#pragma unroll
        for (int f = 0; f < 64; f++) {
            float d = xj[f] - xi[f] + 1e-12f;
            s = fmaf(d, d, s);
        }
        dst_[tid] = sqrtf(s);
    }
    __syncthreads();

    // ---- build h0 fp16 hi/lo: 64 x 256 ----
    {
        int r = tid >> 1, kq = (tid & 1) * 128;
        float dj = dst_[r];
        const float4* q4 = (const float4*)(g_Q + ((size_t)(b * 64 + r)) * 256);
        __half2* ahp = (__half2*)(Ah + r * PA);
        __half2* alp = (__half2*)(Al + r * PA);
#pragma unroll
        for (int g4 = 0; g4 < 32; g4++) {
            int k = kq + g4 * 4;
            float4 q = q4[k >> 2];
            float v0 = lrelu(pv[k + 0] + q.x + dj * w0s[k + 0]);
            float v1 = lrelu(pv[k + 1] + q.y + dj * w0s[k + 1]);
            float v2 = lrelu(pv[k + 2] + q.z + dj * w0s[k + 2]);
            float v3 = lrelu(pv[k + 3] + q.w + dj * w0s[k + 3]);
            __half h0 = __float2half_rn(v0), h1 = __float2half_rn(v1);
            __half h2 = __float2half_rn(v2), h3 = __float2half_rn(v3);
            ahp[(k >> 1) + 0] = __halves2half2(h0, h1);
            ahp[(k >> 1) + 1] = __halves2half2(h2, h3);
            alp[(k >> 1) + 0] = __halves2half2(
                __float2half_rn(v0 - __half2float(h0)),
                __float2half_rn(v1 - __half2float(h1)));
            alp[(k >> 1) + 1] = __halves2half2(
                __float2half_rn(v2 - __half2float(h2)),
                __float2half_rn(v3 - __half2float(h3)));
        }
    }

    // ---- ldmatrix lane address components (bytes) ----
    // A x4: lanes 0-7 rows 0-7 @k0 | 8-15 rows 8-15 @k0 | 16-23 rows 0-7 @k8 | 24-31 rows 8-15 @k8
    const unsigned aRow = lane & 15;
    const unsigned aK   = (lane >> 4) << 3;
    const unsigned aOff = (aRow * PA + aK) * 2;
    const unsigned aHB  = smb + OFF_AH + aOff;
    const unsigned aLB  = smb + OFF_AL + aOff;
    // B x4 (2 n-tiles): lanes 0-7 n0-7@k0 | 8-15 n0-7@k8 | 16-23 n8-15@k0 | 24-31 n8-15@k8
    const unsigned bN  = (lane & 7) + ((lane >> 4) << 3);
    const unsigned bK  = ((lane >> 3) & 1) << 3;
    const unsigned bOff = (bN * PB + bK) * 2;
    // B x2 (1 n-tile): lanes 0-7 n0-7@k0 | 8-15 n0-7@k8
    const unsigned bOff2 = ((lane & 7) * PB + (((lane >> 3) & 1) << 3)) * 2;

    // =================== GEMM1: h1 = lrelu(h0 @ W1 + b1) ====================
    float acc[4][8][4];
#pragma unroll
    for (int mf = 0; mf < 4; mf++)
#pragma unroll
        for (int nf = 0; nf < 8; nf++)
#pragma unroll
            for (int e = 0; e < 4; e++) acc[mf][nf][e] = 0.f;

    for (int tc = 0; tc < 8; tc++) {
        int buf = tc & 1;
        CP_WAIT0();
        __syncthreads();
        if (tc < 7) loadB(g_B1 + (size_t)(tc + 1) * B1_CHUNK_HALVES, buf ^ 1, B1_CHUNK_BYTES);
        const unsigned bBase = smb + OFF_B + buf * B1_CHUNK_BYTES + w * (64 * PB * 2);
#pragma unroll
        for (int grp = 0; grp < 2; grp++) {
            const unsigned kaB = (tc * KCH + grp * 16) * 2;   // A: global k offset
            const unsigned kbB = (grp * 16) * 2;              // B: chunk-local k offset
            uint32_t ah[4][4], al[4][4];
#pragma unroll
            for (int mf = 0; mf < 4; mf++) {
                LDSM4(ah[mf][0], ah[mf][1], ah[mf][2], ah[mf][3],
                      aHB + mf * (16 * PA * 2) + kaB);
                LDSM4(al[mf][0], al[mf][1], al[mf][2], al[mf][3],
                      aLB + mf * (16 * PA * 2) + kaB);
            }
            uint32_t bf[4][4];
#pragma unroll
            for (int p = 0; p < 4; p++)
                LDSM4(bf[p][0], bf[p][1], bf[p][2], bf[p][3],
                      bBase + bOff + p * (16 * PB * 2) + kbB);
#pragma unroll
            for (int p = 0; p < 4; p++)
#pragma unroll
                for (int q = 0; q < 2; q++) {
                    int nf = 2 * p + q;
                    uint32_t bb[2] = { bf[p][2 * q], bf[p][2 * q + 1] };
#pragma unroll
                    for (int mf = 0; mf < 4; mf++) hmma(acc[mf][nf], ah[mf], bb);
#pragma unroll
                    for (int mf = 0; mf < 4; mf++) hmma(acc[mf][nf], al[mf], bb);
                }
        }
    }
    __syncthreads();
    loadB(g_B2, 0, B2_CHUNK_BYTES);   // prefetch GEMM2 chunk 0

    // ---- h1 epilogue: bias + lrelu, split fp16 hi/lo, overwrite A ----
    {
        const int g = lane >> 2, tig = lane & 3;
#pragma unroll
        for (int mf = 0; mf < 4; mf++) {
            int row0 = mf * 16 + g, row1 = row0 + 8;
#pragma unroll
            for (int nf = 0; nf < 8; nf++) {
                int col = w * 64 + nf * 8 + 2 * tig;
                float ba = b1s[col], bb = b1s[col + 1];
                float v00 = lrelu(acc[mf][nf][0] + ba), v01 = lrelu(acc[mf][nf][1] + bb);
                float v10 = lrelu(acc[mf][nf][2] + ba), v11 = lrelu(acc[mf][nf][3] + bb);
                __half h00 = __float2half_rn(v00), h01 = __float2half_rn(v01);
                __half h10 = __float2half_rn(v10), h11 = __float2half_rn(v11);
                *(__half2*)(Ah + row0 * PA + col) = __halves2half2(h00, h01);
                *(__half2*)(Ah + row1 * PA + col) = __halves2half2(h10, h11);
                *(__half2*)(Al + row0 * PA + col) = __halves2half2(
                    __float2half_rn(v00 - __half2float(h00)),
                    __float2half_rn(v01 - __half2float(h01)));
                *(__half2*)(Al + row1 * PA + col) = __halves2half2(
                    __float2half_rn(v10 - __half2float(h10)),
                    __float2half_rn(v11 - __half2float(h11)));
            }
        }
    }
    __syncthreads();

    // =================== GEMM2: h2 = lrelu(h1 @ W2 + b2) ====================
    float ac2[4][3][4];
#pragma unroll
    for (int mf = 0; mf < 4; mf++)
#pragma unroll
        for (int nf = 0; nf < 3; nf++)
#pragma unroll
            for (int e = 0; e < 4; e++) ac2[mf][nf][e] = 0.f;

    for (int tc = 0; tc < 8; tc++) {
        int buf = tc & 1;
        CP_WAIT0();
        __syncthreads();
        if (tc < 7) loadB(g_B2 + (size_t)(tc + 1) * B2_CHUNK_HALVES, buf ^ 1, B2_CHUNK_BYTES);
        const unsigned bBase = smb + OFF_B + buf * B1_CHUNK_BYTES + w * (24 * PB * 2);
#pragma unroll
        for (int grp = 0; grp < 2; grp++) {
            const unsigned kaB = (tc * KCH + grp * 16) * 2;   // A: global k offset
            const unsigned kbB = (grp * 16) * 2;              // B: chunk-local k offset
            uint32_t ah[4][4], al[4][4];
#pragma unroll
            for (int mf = 0; mf < 4; mf++) {
                LDSM4(ah[mf][0], ah[mf][1], ah[mf][2], ah[mf][3],
                      aHB + mf * (16 * PA * 2) + kaB);
                LDSM4(al[mf][0], al[mf][1], al[mf][2], al[mf][3],
                      aLB + mf * (16 * PA * 2) + kaB);
            }
            uint32_t bf01[4], bf2[2];
            LDSM4(bf01[0], bf01[1], bf01[2], bf01[3], bBase + bOff + kbB);
            LDSM2(bf2[0], bf2[1], bBase + 16 * PB * 2 + bOff2 + kbB);
#pragma unroll
            for (int nf = 0; nf < 3; nf++) {
                uint32_t bb[2];
                if (nf < 2) { bb[0] = bf01[2 * nf]; bb[1] = bf01[2 * nf + 1]; }
                else        { bb[0] = bf2[0];       bb[1] = bf2[1]; }
#pragma unroll
                for (int mf = 0; mf < 4; mf++) hmma(ac2[mf][nf], ah[mf], bb);
#pragma unroll
                for (int mf = 0; mf < 4; mf++) hmma(ac2[mf][nf], al[mf], bb);
            }
        }
    }
    __syncthreads();

    // ---- h2 epilogue: bias + lrelu, stage fp32 [64][100], column-sum over j ----
    float* stage = (float*)(sm + OFF_B);
    {
        const int g = lane >> 2, tig = lane & 3;
#pragma unroll
        for (int mf = 0; mf < 4; mf++) {
            int row0 = mf * 16 + g, row1 = row0 + 8;
#pragma unroll
            for (int nf = 0; nf < 3; nf++) {
                int col = w * 24 + nf * 8 + 2 * tig;
                float ba = b2s[col], bb = b2s[col + 1];
                stage[row0 * 100 + col]     = lrelu(ac2[mf][nf][0] + ba);
                stage[row0 * 100 + col + 1] = lrelu(ac2[mf][nf][1] + bb);
                stage[row1 * 100 + col]     = lrelu(ac2[mf][nf][2] + ba);
                stage[row1 * 100 + col + 1] = lrelu(ac2[mf][nf][3] + bb);
            }
        }
    }
    __syncthreads();
    if (tid < 96) {
        float s = 0.f;
#pragma unroll 8
        for (int r = 0; r < 64; r++) s += stage[r * 100 + tid];
        g_AGG[(size_t)(b * 64 + i) * C2 + tid] = s;
    }
}

// ---------------- node MLP (fp32) --------------------------------------------
__global__ __launch_bounds__(256) void node_kernel(
    const float* __restrict__ x,
    const float* __restrict__ Wn0, const float* __restrict__ bn0,
    const float* __restrict__ Wn1, const float* __restrict__ bn1,
    float* __restrict__ out)
{
    __shared__ float t160[16 * 160];
    __shared__ float zs[16 * 256];
    const int r0 = blockIdx.x * 16;
    const int tid = threadIdx.x;

    for (int idx = tid; idx < 16 * 160; idx += 256) {
        int rr = idx / 160, k = idx - rr * 160;
        t160[idx] = (k < 96) ? g_AGG[(size_t)(r0 + rr) * 96 + k]
                             : x[(size_t)(r0 + rr) * 64 + (k - 96)];
    }
    __syncthreads();
    {
        const int c = tid;
        float acc[16];
        float bb = bn0[c];
#pragma unroll
        for (int r = 0; r < 16; r++) acc[r] = bb;
#pragma unroll 4
        for (int k = 0; k < 160; k++) {
            float wv = Wn0[(size_t)k * 256 + c];
#pragma unroll
            for (int r = 0; r < 16; r++) acc[r] = fmaf(t160[r * 160 + k], wv, acc[r]);
        }
#pragma unroll
        for (int r = 0; r < 16; r++) zs[r * 256 + c] = lrelu(acc[r]);
    }
    __syncthreads();
    for (int pass = 0; pass < 4; pass++) {
        int r = pass * 4 + (tid >> 6), c = tid & 63;
        float a = bn1[c];
#pragma unroll 8
        for (int k = 0; k < 256; k++)
            a = fmaf(zs[r * 256 + k], Wn1[(size_t)k * 64 + c], a);
        out[(size_t)(r0 + r) * 64 + c] = a;
    }
}

// ---------------- launch -----------------------------------------------------
extern "C" void kernel_launch(void* const* d_in, const int* in_sizes, int n_in,
                              void* d_out, int out_size)
{
    const float* x    = (const float*)d_in[0];
    const float* feW0 = (const float*)d_in[1];
    const float* feb0 = (const float*)d_in[2];
    const float* feW1 = (const float*)d_in[3];
    const float* feb1 = (const float*)d_in[4];
    const float* feW2 = (const float*)d_in[5];
    const float* feb2 = (const float*)d_in[6];
    const float* fnW0 = (const float*)d_in[7];
    const float* fnb0 = (const float*)d_in[8];
    const float* fnW1 = (const float*)d_in[9];
    const float* fnb1 = (const float*)d_in[10];
    float* out = (float*)d_out;

    cudaFuncSetAttribute(mp_main, cudaFuncAttributeMaxDynamicSharedMemorySize, SMEM_SZ);

    pq_kernel<<<512, 256>>>(x, feW0, feb0);
    prep_w<<<352, 256>>>(feW1, feW2);
    prep_vec<<<1, 256>>>(feW0, feb1, feb2);
    mp_main<<<BATCH * NN, THREADS, SMEM_SZ>>>(x);
    node_kernel<<<512, 256>>>(x, fnW0, fnb0, fnW1, fnb1, out);
}